// round 1
// baseline (speedup 1.0000x reference)
#include <cuda_runtime.h>
#include <cstdint>
#include <cstddef>

#define N 4096
#define NNELEM ((size_t)N * (size_t)N)

// ---------------- static scratch (allocation-free rule) ----------------
__device__ float g_X [NNELEM];
__device__ float g_X2[NNELEM];
__device__ float g_X3[NNELEM];
__device__ float g_T0[NNELEM];
__device__ float g_T1[NNELEM];
__device__ float g_H [NNELEM];
__device__ float g_HT[NNELEM];
__device__ float g_thr[N];

// ---------------- elementwise: X = a * adj ----------------
__global__ __launch_bounds__(256) void scale_kernel(const float* __restrict__ in,
                                                    float* __restrict__ out, float a) {
    size_t i = ((size_t)blockIdx.x * 256 + threadIdx.x) * 4;
    float4 v = *(const float4*)(in + i);
    v.x *= a; v.y *= a; v.z *= a; v.w *= a;
    *(float4*)(out + i) = v;
}

// ---------------- elementwise: out = ci*I + cx*X + cx2*X2 (+ Add) ----------------
__global__ __launch_bounds__(256) void poly_combine(const float* __restrict__ X,
                                                    const float* __restrict__ X2,
                                                    const float* __restrict__ Add,
                                                    float* __restrict__ out,
                                                    float ci, float cx, float cx2,
                                                    int useAdd) {
    size_t i = (size_t)blockIdx.x * 256 + threadIdx.x;
    int r = (int)(i >> 12);
    int c = (int)(i & (N - 1));
    float v = cx * X[i] + cx2 * X2[i];
    if (useAdd) v += Add[i];
    if (r == c) v += ci;
    out[i] = v;
}

// ---------------- fp32 SIMT GEMM: C = A * B (row-major, N x N) ----------------
#define BM 128
#define BN 128
#define BK 8
__global__ __launch_bounds__(256) void sgemm(const float* __restrict__ A,
                                             const float* __restrict__ B,
                                             float* __restrict__ C) {
    __shared__ float As[BK][BM];
    __shared__ float Bs[BK][BN];

    const int bx = blockIdx.x;   // N dim
    const int by = blockIdx.y;   // M dim
    const int tid = threadIdx.x;
    const int tx = tid & 15;     // 0..15 -> 8 cols each
    const int ty = tid >> 4;     // 0..15 -> 8 rows each

    const float* Ablk = A + (size_t)by * BM * N;
    const float* Bblk = B + (size_t)bx * BN;

    // A tile loads: 128x8 = 256 float4; thread t -> row t/2, col (t%2)*4
    const int arow = tid >> 1;
    const int acol = (tid & 1) * 4;
    // B tile loads: 8x128 = 256 float4; thread t -> row t/32, col (t%32)*4
    const int brow = tid >> 5;
    const int bcol = (tid & 31) * 4;

    float acc[8][8];
#pragma unroll
    for (int i = 0; i < 8; i++)
#pragma unroll
        for (int j = 0; j < 8; j++) acc[i][j] = 0.f;

    for (int k0 = 0; k0 < N; k0 += BK) {
        float4 av = *(const float4*)(Ablk + (size_t)arow * N + (k0 + acol));
        float4 bv = *(const float4*)(Bblk + (size_t)(k0 + brow) * N + bcol);
        __syncthreads();
        As[acol + 0][arow] = av.x;
        As[acol + 1][arow] = av.y;
        As[acol + 2][arow] = av.z;
        As[acol + 3][arow] = av.w;
        *(float4*)&Bs[brow][bcol] = bv;
        __syncthreads();
#pragma unroll
        for (int k = 0; k < BK; k++) {
            float4 a0 = *(const float4*)&As[k][ty * 8 + 0];
            float4 a1 = *(const float4*)&As[k][ty * 8 + 4];
            float4 b0 = *(const float4*)&Bs[k][tx * 8 + 0];
            float4 b1 = *(const float4*)&Bs[k][tx * 8 + 4];
            float a[8] = {a0.x, a0.y, a0.z, a0.w, a1.x, a1.y, a1.z, a1.w};
            float b[8] = {b0.x, b0.y, b0.z, b0.w, b1.x, b1.y, b1.z, b1.w};
#pragma unroll
            for (int i = 0; i < 8; i++)
#pragma unroll
                for (int j = 0; j < 8; j++) acc[i][j] += a[i] * b[j];
        }
    }

    float* Cblk = C + (size_t)(by * BM + ty * 8) * N + (size_t)bx * BN + tx * 8;
#pragma unroll
    for (int i = 0; i < 8; i++) {
        *(float4*)(Cblk + (size_t)i * N + 0) = make_float4(acc[i][0], acc[i][1], acc[i][2], acc[i][3]);
        *(float4*)(Cblk + (size_t)i * N + 4) = make_float4(acc[i][4], acc[i][5], acc[i][6], acc[i][7]);
    }
}

// ---------------- per-row 16th-largest threshold (exact radix select) ----------------
__global__ __launch_bounds__(256) void topk_thresh(const float* __restrict__ H,
                                                   float* __restrict__ thr) {
    __shared__ unsigned sk[N];       // 16 KB
    __shared__ int swarp[8];
    __shared__ int stot;
    const int row = blockIdx.x;
    const float* h = H + (size_t)row * N;

    for (int j = threadIdx.x; j < N; j += 256) {
        unsigned u = __float_as_uint(h[j]);
        sk[j] = (u & 0x80000000u) ? ~u : (u | 0x80000000u);  // order-preserving key
    }
    __syncthreads();

    unsigned v = 0;
    for (int bit = 31; bit >= 0; bit--) {
        unsigned cand = v | (1u << bit);
        int c = 0;
        for (int j = threadIdx.x; j < N; j += 256) c += (sk[j] >= cand);
        c = __reduce_add_sync(0xffffffffu, c);
        if ((threadIdx.x & 31) == 0) swarp[threadIdx.x >> 5] = c;
        __syncthreads();
        if (threadIdx.x == 0) {
            int t = 0;
#pragma unroll
            for (int w = 0; w < 8; w++) t += swarp[w];
            stot = t;
        }
        __syncthreads();
        if (stot >= 16) v = cand;   // same decision in every thread
        __syncthreads();
    }
    if (threadIdx.x == 0) {
        unsigned u = (v & 0x80000000u) ? (v & 0x7FFFFFFFu) : ~v;  // inverse transform
        thr[row] = __uint_as_float(u);
    }
}

// ---------------- tiled transpose ----------------
__global__ void transpose_kernel(const float* __restrict__ in, float* __restrict__ out) {
    __shared__ float tile[32][33];
    int x = blockIdx.x * 32 + threadIdx.x;
    int y = blockIdx.y * 32 + threadIdx.y;
#pragma unroll
    for (int i = 0; i < 32; i += 8)
        tile[threadIdx.y + i][threadIdx.x] = in[(size_t)(y + i) * N + x];
    __syncthreads();
    x = blockIdx.y * 32 + threadIdx.x;
    y = blockIdx.x * 32 + threadIdx.y;
#pragma unroll
    for (int i = 0; i < 32; i += 8)
        out[(size_t)(y + i) * N + x] = tile[threadIdx.x][threadIdx.y + i];
}

// ---------------- mask + symmetrize + I + row-normalize ----------------
__global__ __launch_bounds__(256) void finalize_kernel(const float* __restrict__ H,
                                                       const float* __restrict__ HT,
                                                       const float* __restrict__ thr,
                                                       float* __restrict__ out) {
    __shared__ float sthr[N];        // 16 KB
    __shared__ float swarp[8];
    __shared__ float sinv;
    const int row = blockIdx.x;
    for (int j = threadIdx.x; j < N; j += 256) sthr[j] = thr[j];
    __syncthreads();

    const float ti = sthr[row];
    const float* h  = H  + (size_t)row * N;
    const float* ht = HT + (size_t)row * N;

    float s = 0.f;
    for (int j = threadIdx.x; j < N; j += 256) {
        float hij = h[j], hji = ht[j];
        if (hij >= ti || hji >= sthr[j]) s += 0.5f * (hij + hji);
    }
#pragma unroll
    for (int o = 16; o; o >>= 1) s += __shfl_down_sync(0xffffffffu, s, o);
    if ((threadIdx.x & 31) == 0) swarp[threadIdx.x >> 5] = s;
    __syncthreads();
    if (threadIdx.x == 0) {
        float t = 0.f;
#pragma unroll
        for (int w = 0; w < 8; w++) t += swarp[w];
        sinv = 1.0f / (t + 1.0f);    // deg = masked row sum + self-loop
    }
    __syncthreads();
    const float inv = sinv;

    for (int j = threadIdx.x; j < N; j += 256) {
        float hij = h[j], hji = ht[j];
        float v = (hij >= ti || hji >= sthr[j]) ? 0.5f * (hij + hji) : 0.f;
        if (j == row) v += 1.0f;
        out[(size_t)row * N + j] = v * inv;
    }
}

// ---------------- launch ----------------
extern "C" void kernel_launch(void* const* d_in, const int* in_sizes, int n_in,
                              void* d_out, int out_size) {
    const float* adj = (const float*)d_in[0];
    float* out = (float*)d_out;

    float *X, *X2, *X3, *T0, *T1, *H, *HT, *thr;
    cudaGetSymbolAddress((void**)&X,  g_X);
    cudaGetSymbolAddress((void**)&X2, g_X2);
    cudaGetSymbolAddress((void**)&X3, g_X3);
    cudaGetSymbolAddress((void**)&T0, g_T0);
    cudaGetSymbolAddress((void**)&T1, g_T1);
    cudaGetSymbolAddress((void**)&H,  g_H);
    cudaGetSymbolAddress((void**)&HT, g_HT);
    cudaGetSymbolAddress((void**)&thr, g_thr);

    const int ebNvec = (int)(NNELEM / 4 / 256);   // float4 elementwise blocks
    const int ebN    = (int)(NNELEM / 256);       // scalar elementwise blocks
    dim3 ggrid(N / BN, N / BM);

    // X = -(T/4) * adj    (scaling-and-squaring with s = 2, T = 5)
    scale_kernel<<<ebNvec, 256>>>(adj, X, -1.25f);

    // X2 = X*X ; X3 = X2*X
    sgemm<<<ggrid, 256>>>(X, X, X2);
    sgemm<<<ggrid, 256>>>(X2, X, X3);

    // Paterson-Stockmeyer degree-8 Taylor:
    // A2 = I/720 + X/5040 + X2/40320
    poly_combine<<<ebN, 256>>>(X, X2, nullptr, T0,
                               1.0f / 720.0f, 1.0f / 5040.0f, 1.0f / 40320.0f, 0);
    sgemm<<<ggrid, 256>>>(X3, T0, T1);                 // T1 = X3*A2
    // T0 = A1 + T1 = I/6 + X/24 + X2/120 + T1
    poly_combine<<<ebN, 256>>>(X, X2, T1, T0,
                               1.0f / 6.0f, 1.0f / 24.0f, 1.0f / 120.0f, 1);
    sgemm<<<ggrid, 256>>>(X3, T0, T1);                 // T1 = X3*(A1 + X3*A2)
    // T0 = P = I + X + X2/2 + T1
    poly_combine<<<ebN, 256>>>(X, X2, T1, T0, 1.0f, 1.0f, 0.5f, 1);

    // heat = P^4 (two squarings)
    sgemm<<<ggrid, 256>>>(T0, T0, T1);                 // T1 = P^2
    sgemm<<<ggrid, 256>>>(T1, T1, H);                  // H  = P^4 = expm(-5*adj)

    // top-16 per-row thresholds, transpose, finalize
    topk_thresh<<<N, 256>>>(H, thr);
    transpose_kernel<<<dim3(N / 32, N / 32), dim3(32, 8)>>>(H, HT);
    finalize_kernel<<<N, 256>>>(H, HT, thr, out);
}

// round 5
// speedup vs baseline: 3.0224x; 3.0224x over previous
#include <cuda_runtime.h>
#include <cuda_bf16.h>
#include <cstdint>
#include <cstddef>

#define N 4096
#define NNELEM ((size_t)N * (size_t)N)

// ---------------- static scratch (allocation-free rule) ----------------
__device__ float g_X [NNELEM];
__device__ float g_X2[NNELEM];
__device__ float g_T0[NNELEM];
__device__ float g_T1[NNELEM];
__device__ float g_H [NNELEM];
__device__ float g_HT[NNELEM];
__device__ float g_thr[N];
__device__ __nv_bfloat16 g_Ahi[NNELEM];
__device__ __nv_bfloat16 g_Alo[NNELEM];
__device__ __nv_bfloat16 g_Bhi[NNELEM];
__device__ __nv_bfloat16 g_Blo[NNELEM];
__device__ __nv_bfloat16 g_A3hi[NNELEM];
__device__ __nv_bfloat16 g_A3lo[NNELEM];

// ---------------- helpers ----------------
__device__ __forceinline__ uint32_t smem_u32(const void* p) {
    return (uint32_t)__cvta_generic_to_shared(p);
}
__device__ __forceinline__ void cp16(uint32_t s, const void* g) {
    asm volatile("cp.async.cg.shared.global [%0], [%1], 16;" :: "r"(s), "l"(g));
}
#define SWZ(x) ((x) ^ (((x) >> 3) & 0x70))

__device__ __forceinline__ unsigned short bfbits(float f) {
    __nv_bfloat16 h = __float2bfloat16(f);
    return *reinterpret_cast<unsigned short*>(&h);
}
__device__ __forceinline__ float bf2f(unsigned short u) {
    __nv_bfloat16 h = *reinterpret_cast<__nv_bfloat16*>(&u);
    return __bfloat162float(h);
}

// ---------------- elementwise: X = a * adj ----------------
__global__ __launch_bounds__(256) void scale_kernel(const float* __restrict__ in,
                                                    float* __restrict__ out, float a) {
    size_t i = ((size_t)blockIdx.x * 256 + threadIdx.x) * 4;
    float4 v = *(const float4*)(in + i);
    v.x *= a; v.y *= a; v.z *= a; v.w *= a;
    *(float4*)(out + i) = v;
}

// ---------------- split fp32 -> bf16 hi/lo, row-major ----------------
__global__ __launch_bounds__(256) void split_rm(const float* __restrict__ in,
                                                __nv_bfloat16* __restrict__ hi,
                                                __nv_bfloat16* __restrict__ lo) {
    size_t i = ((size_t)blockIdx.x * 256 + threadIdx.x) * 4;
    float4 v = *(const float4*)(in + i);
    unsigned short h0 = bfbits(v.x), h1 = bfbits(v.y), h2 = bfbits(v.z), h3 = bfbits(v.w);
    unsigned short l0 = bfbits(v.x - bf2f(h0)), l1 = bfbits(v.y - bf2f(h1));
    unsigned short l2 = bfbits(v.z - bf2f(h2)), l3 = bfbits(v.w - bf2f(h3));
    uint2 H = make_uint2((unsigned)h0 | ((unsigned)h1 << 16), (unsigned)h2 | ((unsigned)h3 << 16));
    uint2 L = make_uint2((unsigned)l0 | ((unsigned)l1 << 16), (unsigned)l2 | ((unsigned)l3 << 16));
    *(uint2*)((unsigned short*)hi + i) = H;
    *(uint2*)((unsigned short*)lo + i) = L;
}

// ---------------- split fp32 -> bf16 hi/lo, transposed ----------------
__global__ void split_tr(const float* __restrict__ in,
                         __nv_bfloat16* __restrict__ hi,
                         __nv_bfloat16* __restrict__ lo) {
    __shared__ float tile[32][33];
    int x = blockIdx.x * 32 + threadIdx.x;
    int y = blockIdx.y * 32 + threadIdx.y;
#pragma unroll
    for (int i = 0; i < 32; i += 8)
        tile[threadIdx.y + i][threadIdx.x] = in[(size_t)(y + i) * N + x];
    __syncthreads();
    x = blockIdx.y * 32 + threadIdx.x;
    y = blockIdx.x * 32 + threadIdx.y;
#pragma unroll
    for (int i = 0; i < 32; i += 8) {
        float v = tile[threadIdx.x][threadIdx.y + i];
        unsigned short h = bfbits(v);
        unsigned short l = bfbits(v - bf2f(h));
        size_t o = (size_t)(y + i) * N + x;
        ((unsigned short*)hi)[o] = h;
        ((unsigned short*)lo)[o] = l;
    }
}

// ---------------- elementwise: out = ci*I + cx*X + cx2*X2 (+ Add) ----------------
__global__ __launch_bounds__(256) void poly_combine(const float* __restrict__ X,
                                                    const float* __restrict__ X2,
                                                    const float* __restrict__ Add,
                                                    float* __restrict__ out,
                                                    float ci, float cx, float cx2,
                                                    int useAdd) {
    size_t i = (size_t)blockIdx.x * 256 + threadIdx.x;
    int r = (int)(i >> 12);
    int c = (int)(i & (N - 1));
    float v = cx * X[i] + cx2 * X2[i];
    if (useAdd) v += Add[i];
    if (r == c) v += ci;
    out[i] = v;
}

// ================= mma.sync bf16x3 GEMM: C = A*B (fp32-equivalent) =================
// A' = [Ahi | Ahi | Alo] along K, B'^T = [Bhi | Blo | Bhi]  (B given as [N,K] row-major)
#define BM 128
#define BN 256
#define BK 64
#define STAGES 3
#define NCHUNK 192                           // 3 * 4096 / 64
#define STAGE_BYTES (BM * 128 + BN * 128)    // 49152
#define GEMM_SMEM (STAGES * STAGE_BYTES)     // 147456

__device__ __forceinline__ void ldsm4(uint32_t& r0, uint32_t& r1, uint32_t& r2, uint32_t& r3,
                                      uint32_t addr) {
    asm volatile("ldmatrix.sync.aligned.m8n8.x4.shared.b16 {%0,%1,%2,%3}, [%4];"
                 : "=r"(r0), "=r"(r1), "=r"(r2), "=r"(r3) : "r"(addr));
}
__device__ __forceinline__ void mma16816(float* c, const uint32_t* a, uint32_t b0, uint32_t b1) {
    asm volatile("mma.sync.aligned.m16n8k16.row.col.f32.bf16.bf16.f32 "
                 "{%0,%1,%2,%3}, {%4,%5,%6,%7}, {%8,%9}, {%0,%1,%2,%3};"
                 : "+f"(c[0]), "+f"(c[1]), "+f"(c[2]), "+f"(c[3])
                 : "r"(a[0]), "r"(a[1]), "r"(a[2]), "r"(a[3]), "r"(b0), "r"(b1));
}

__global__ void __launch_bounds__(256, 1)
gemm_bf16x3(const __nv_bfloat16* __restrict__ Ahi, const __nv_bfloat16* __restrict__ Alo,
            const __nv_bfloat16* __restrict__ Bhi, const __nv_bfloat16* __restrict__ Blo,
            float* __restrict__ C) {
    extern __shared__ char smem[];
    const uint32_t sb = smem_u32(smem);
    const int tid = threadIdx.x;
    const int wid = tid >> 5;
    const int lane = tid & 31;
    const int wm = wid & 1;          // 2 warps over M (64 rows each)
    const int wn = wid >> 1;         // 4 warps over N (64 cols each)
    const int m0 = blockIdx.y * BM;
    const int n0 = blockIdx.x * BN;

    float acc[4][8][4];
#pragma unroll
    for (int i = 0; i < 4; i++)
#pragma unroll
        for (int j = 0; j < 8; j++)
#pragma unroll
            for (int k = 0; k < 4; k++) acc[i][j][k] = 0.f;

    auto load_chunk = [&](int c) {
        const int seg = c >> 6;            // 0,1,2
        const int k0 = (c & 63) << 6;      // K offset within 4096
        const __nv_bfloat16* A = (seg == 2) ? Alo : Ahi;
        const __nv_bfloat16* B = (seg == 1) ? Blo : Bhi;
        const uint32_t sA = sb + (c % STAGES) * STAGE_BYTES;
        const uint32_t sB = sA + BM * 128;
#pragma unroll
        for (int i = 0; i < 4; i++) {      // A: 1024 x 16B
            int q = tid + i * 256;
            int row = q >> 3, c16 = q & 7;
            cp16(sA + SWZ(row * 128 + c16 * 16),
                 A + (((size_t)(m0 + row)) << 12) + k0 + (c16 << 3));
        }
#pragma unroll
        for (int i = 0; i < 8; i++) {      // B: 2048 x 16B
            int q = tid + i * 256;
            int row = q >> 3, c16 = q & 7;
            cp16(sB + SWZ(row * 128 + c16 * 16),
                 B + (((size_t)(n0 + row)) << 12) + k0 + (c16 << 3));
        }
        asm volatile("cp.async.commit_group;" ::: "memory");
    };

    load_chunk(0);
    load_chunk(1);

    const int t = lane >> 3;     // 8x8-tile index within ldmatrix.x4
    const int r = lane & 7;      // row within 8x8 tile

    for (int c = 0; c < NCHUNK; c++) {
        asm volatile("cp.async.wait_group 1;" ::: "memory");
        __syncthreads();
        if (c + 2 < NCHUNK) load_chunk(c + 2);

        const uint32_t sA = sb + (c % STAGES) * STAGE_BYTES;
        const uint32_t sB = sA + BM * 128;

#pragma unroll
        for (int kk = 0; kk < 4; kk++) {   // 4 x k16 per chunk
            uint32_t a[4][4], b[4][4];
#pragma unroll
            for (int mt = 0; mt < 4; mt++) {
                int mrow = wm * 64 + mt * 16 + (t & 1) * 8 + r;
                ldsm4(a[mt][0], a[mt][1], a[mt][2], a[mt][3],
                      sA + SWZ(mrow * 128 + kk * 32 + (t >> 1) * 16));
            }
#pragma unroll
            for (int j = 0; j < 4; j++) {
                int nrow = wn * 64 + j * 16 + (t >> 1) * 8 + r;
                ldsm4(b[j][0], b[j][1], b[j][2], b[j][3],
                      sB + SWZ(nrow * 128 + kk * 32 + (t & 1) * 16));
            }
#pragma unroll
            for (int mt = 0; mt < 4; mt++)
#pragma unroll
                for (int nt = 0; nt < 8; nt++)
                    mma16816(acc[mt][nt], a[mt], b[nt >> 1][(nt & 1) * 2],
                             b[nt >> 1][(nt & 1) * 2 + 1]);
        }
        __syncthreads();
    }

    // epilogue: direct fp32 stores
    const int gp = lane >> 2, q = lane & 3;
#pragma unroll
    for (int mt = 0; mt < 4; mt++) {
        int m = m0 + wm * 64 + mt * 16 + gp;
        float* row0 = C + (size_t)m * N + n0 + wn * 64;
        float* row1 = row0 + (size_t)8 * N;
#pragma unroll
        for (int nt = 0; nt < 8; nt++) {
            *(float2*)(row0 + nt * 8 + q * 2) = make_float2(acc[mt][nt][0], acc[mt][nt][1]);
            *(float2*)(row1 + nt * 8 + q * 2) = make_float2(acc[mt][nt][2], acc[mt][nt][3]);
        }
    }
}

// ---------------- per-row 16th-largest threshold (exact radix select) ----------------
__global__ __launch_bounds__(256) void topk_thresh(const float* __restrict__ H,
                                                   float* __restrict__ thr) {
    __shared__ unsigned sk[N];
    __shared__ int swarp[8];
    __shared__ int stot;
    const int row = blockIdx.x;
    const float* h = H + (size_t)row * N;

    for (int j = threadIdx.x; j < N; j += 256) {
        unsigned u = __float_as_uint(h[j]);
        sk[j] = (u & 0x80000000u) ? ~u : (u | 0x80000000u);
    }
    __syncthreads();

    unsigned v = 0;
    for (int bit = 31; bit >= 0; bit--) {
        unsigned cand = v | (1u << bit);
        int c = 0;
        for (int j = threadIdx.x; j < N; j += 256) c += (sk[j] >= cand);
        c = __reduce_add_sync(0xffffffffu, c);
        if ((threadIdx.x & 31) == 0) swarp[threadIdx.x >> 5] = c;
        __syncthreads();
        if (threadIdx.x == 0) {
            int tt = 0;
#pragma unroll
            for (int w = 0; w < 8; w++) tt += swarp[w];
            stot = tt;
        }
        __syncthreads();
        if (stot >= 16) v = cand;
        __syncthreads();
    }
    if (threadIdx.x == 0) {
        unsigned u = (v & 0x80000000u) ? (v & 0x7FFFFFFFu) : ~v;
        thr[row] = __uint_as_float(u);
    }
}

// ---------------- tiled transpose ----------------
__global__ void transpose_kernel(const float* __restrict__ in, float* __restrict__ out) {
    __shared__ float tile[32][33];
    int x = blockIdx.x * 32 + threadIdx.x;
    int y = blockIdx.y * 32 + threadIdx.y;
#pragma unroll
    for (int i = 0; i < 32; i += 8)
        tile[threadIdx.y + i][threadIdx.x] = in[(size_t)(y + i) * N + x];
    __syncthreads();
    x = blockIdx.y * 32 + threadIdx.x;
    y = blockIdx.x * 32 + threadIdx.y;
#pragma unroll
    for (int i = 0; i < 32; i += 8)
        out[(size_t)(y + i) * N + x] = tile[threadIdx.x][threadIdx.y + i];
}

// ---------------- mask + symmetrize + I + row-normalize ----------------
__global__ __launch_bounds__(256) void finalize_kernel(const float* __restrict__ H,
                                                       const float* __restrict__ HT,
                                                       const float* __restrict__ thr,
                                                       float* __restrict__ out) {
    __shared__ float sthr[N];
    __shared__ float swarp[8];
    __shared__ float sinv;
    const int row = blockIdx.x;
    for (int j = threadIdx.x; j < N; j += 256) sthr[j] = thr[j];
    __syncthreads();

    const float ti = sthr[row];
    const float* h  = H  + (size_t)row * N;
    const float* ht = HT + (size_t)row * N;

    float s = 0.f;
    for (int j = threadIdx.x; j < N; j += 256) {
        float hij = h[j], hji = ht[j];
        if (hij >= ti || hji >= sthr[j]) s += 0.5f * (hij + hji);
    }
#pragma unroll
    for (int o = 16; o; o >>= 1) s += __shfl_down_sync(0xffffffffu, s, o);
    if ((threadIdx.x & 31) == 0) swarp[threadIdx.x >> 5] = s;
    __syncthreads();
    if (threadIdx.x == 0) {
        float tt = 0.f;
#pragma unroll
        for (int w = 0; w < 8; w++) tt += swarp[w];
        sinv = 1.0f / (tt + 1.0f);
    }
    __syncthreads();
    const float inv = sinv;

    for (int j = threadIdx.x; j < N; j += 256) {
        float hij = h[j], hji = ht[j];
        float v = (hij >= ti || hji >= sthr[j]) ? 0.5f * (hij + hji) : 0.f;
        if (j == row) v += 1.0f;
        out[(size_t)row * N + j] = v * inv;
    }
}

// ---------------- launch ----------------
extern "C" void kernel_launch(void* const* d_in, const int* in_sizes, int n_in,
                              void* d_out, int out_size) {
    const float* adj = (const float*)d_in[0];
    float* out = (float*)d_out;

    float *X, *X2, *T0, *T1, *H, *HT, *thr;
    __nv_bfloat16 *Ahi, *Alo, *Bhi, *Blo, *A3hi, *A3lo;
    cudaGetSymbolAddress((void**)&X,  g_X);
    cudaGetSymbolAddress((void**)&X2, g_X2);
    cudaGetSymbolAddress((void**)&T0, g_T0);
    cudaGetSymbolAddress((void**)&T1, g_T1);
    cudaGetSymbolAddress((void**)&H,  g_H);
    cudaGetSymbolAddress((void**)&HT, g_HT);
    cudaGetSymbolAddress((void**)&thr, g_thr);
    cudaGetSymbolAddress((void**)&Ahi, g_Ahi);
    cudaGetSymbolAddress((void**)&Alo, g_Alo);
    cudaGetSymbolAddress((void**)&Bhi, g_Bhi);
    cudaGetSymbolAddress((void**)&Blo, g_Blo);
    cudaGetSymbolAddress((void**)&A3hi, g_A3hi);
    cudaGetSymbolAddress((void**)&A3lo, g_A3lo);

    cudaFuncSetAttribute(gemm_bf16x3, cudaFuncAttributeMaxDynamicSharedMemorySize, GEMM_SMEM);

    const int ebv = (int)(NNELEM / 4 / 256);
    const int ebN = (int)(NNELEM / 256);
    dim3 tgrid(N / 32, N / 32), tblk(32, 8);
    dim3 ggrid(N / BN, N / BM);

    // X = -(T/4) * adj   (scaling-and-squaring, s = 2, T = 5)
    scale_kernel<<<ebv, 256>>>(adj, X, -1.25f);
    split_rm<<<ebv, 256>>>(X, Ahi, Alo);
    split_tr<<<tgrid, tblk>>>(X, Bhi, Blo);

    // X2 = X*X
    gemm_bf16x3<<<ggrid, 256, GEMM_SMEM>>>(Ahi, Alo, Bhi, Blo, X2);
    split_rm<<<ebv, 256>>>(X2, Ahi, Alo);

    // X3 = X2*X  (B buffers still hold X^T)
    gemm_bf16x3<<<ggrid, 256, GEMM_SMEM>>>(Ahi, Alo, Bhi, Blo, T1);
    split_rm<<<ebv, 256>>>(T1, A3hi, A3lo);

    // PS degree-8: A2 = I/720 + X/5040 + X2/40320
    poly_combine<<<ebN, 256>>>(X, X2, nullptr, T0,
                               1.0f / 720.0f, 1.0f / 5040.0f, 1.0f / 40320.0f, 0);
    split_tr<<<tgrid, tblk>>>(T0, Bhi, Blo);
    gemm_bf16x3<<<ggrid, 256, GEMM_SMEM>>>(A3hi, A3lo, Bhi, Blo, T1);   // X3*A2

    // A1 + X3*A2
    poly_combine<<<ebN, 256>>>(X, X2, T1, T0,
                               1.0f / 6.0f, 1.0f / 24.0f, 1.0f / 120.0f, 1);
    split_tr<<<tgrid, tblk>>>(T0, Bhi, Blo);
    gemm_bf16x3<<<ggrid, 256, GEMM_SMEM>>>(A3hi, A3lo, Bhi, Blo, T1);   // X3*(A1+X3*A2)

    // P = I + X + X2/2 + above
    poly_combine<<<ebN, 256>>>(X, X2, T1, T0, 1.0f, 1.0f, 0.5f, 1);
    split_rm<<<ebv, 256>>>(T0, Ahi, Alo);
    split_tr<<<tgrid, tblk>>>(T0, Bhi, Blo);
    gemm_bf16x3<<<ggrid, 256, GEMM_SMEM>>>(Ahi, Alo, Bhi, Blo, T1);     // P^2
    split_rm<<<ebv, 256>>>(T1, Ahi, Alo);
    split_tr<<<tgrid, tblk>>>(T1, Bhi, Blo);
    gemm_bf16x3<<<ggrid, 256, GEMM_SMEM>>>(Ahi, Alo, Bhi, Blo, H);      // P^4

    // top-16 thresholds, transpose, finalize
    topk_thresh<<<N, 256>>>(H, thr);
    transpose_kernel<<<tgrid, tblk>>>(H, HT);
    finalize_kernel<<<N, 256>>>(H, HT, thr, out);
}

// round 6
// speedup vs baseline: 3.7839x; 1.2519x over previous
#include <cuda_runtime.h>
#include <cuda_bf16.h>
#include <cstdint>
#include <cstddef>

#define N 4096
#define NNELEM ((size_t)N * (size_t)N)

// ---------------- static scratch (allocation-free rule) ----------------
__device__ float g_X [NNELEM];
__device__ float g_X2[NNELEM];
__device__ float g_T1[NNELEM];
__device__ float g_H [NNELEM];
__device__ float g_HT[NNELEM];
__device__ float g_thr[N];
__device__ __nv_bfloat16 g_P1hi[NNELEM];
__device__ __nv_bfloat16 g_P1lo[NNELEM];
__device__ __nv_bfloat16 g_P2hi[NNELEM];
__device__ __nv_bfloat16 g_P2lo[NNELEM];
__device__ __nv_bfloat16 g_P3hi[NNELEM];
__device__ __nv_bfloat16 g_P3lo[NNELEM];

// ---------------- helpers ----------------
__device__ __forceinline__ uint32_t smem_u32(const void* p) {
    return (uint32_t)__cvta_generic_to_shared(p);
}
__device__ __forceinline__ void cp16(uint32_t s, const void* g) {
    asm volatile("cp.async.cg.shared.global [%0], [%1], 16;" :: "r"(s), "l"(g));
}
#define SWZ(x) ((x) ^ (((x) >> 3) & 0x70))

__device__ __forceinline__ unsigned short bfbits(float f) {
    __nv_bfloat16 h = __float2bfloat16(f);
    return *reinterpret_cast<unsigned short*>(&h);
}
__device__ __forceinline__ float bf2f(unsigned short u) {
    __nv_bfloat16 h = *reinterpret_cast<__nv_bfloat16*>(&u);
    return __bfloat162float(h);
}
__device__ __forceinline__ uint32_t packsplit_hi(float a, float b) {
    return (uint32_t)bfbits(a) | ((uint32_t)bfbits(b) << 16);
}
__device__ __forceinline__ uint32_t packsplit_lo(float a, float b) {
    unsigned short ha = bfbits(a), hb = bfbits(b);
    return (uint32_t)bfbits(a - bf2f(ha)) | ((uint32_t)bfbits(b - bf2f(hb)) << 16);
}

// ---------------- fused scale + row split + transposed split ----------------
// v = a*in ; X=v ; (rhi,rlo)=rowsplit(v) ; (thi,tlo)=trsplit(v)
__global__ void scale_split_both(const float* __restrict__ in, float* __restrict__ X,
                                 __nv_bfloat16* __restrict__ rhi, __nv_bfloat16* __restrict__ rlo,
                                 __nv_bfloat16* __restrict__ thi, __nv_bfloat16* __restrict__ tlo,
                                 float a) {
    __shared__ float tile[32][33];
    int x = blockIdx.x * 32 + threadIdx.x;
    int y = blockIdx.y * 32 + threadIdx.y;
#pragma unroll
    for (int i = 0; i < 32; i += 8) {
        size_t o = (size_t)(y + i) * N + x;
        float v = in[o] * a;
        X[o] = v;
        unsigned short h = bfbits(v);
        ((unsigned short*)rhi)[o] = h;
        ((unsigned short*)rlo)[o] = bfbits(v - bf2f(h));
        tile[threadIdx.y + i][threadIdx.x] = v;
    }
    __syncthreads();
    x = blockIdx.y * 32 + threadIdx.x;
    y = blockIdx.x * 32 + threadIdx.y;
#pragma unroll
    for (int i = 0; i < 32; i += 8) {
        float v = tile[threadIdx.x][threadIdx.y + i];
        unsigned short h = bfbits(v);
        size_t o = (size_t)(y + i) * N + x;
        ((unsigned short*)thi)[o] = h;
        ((unsigned short*)tlo)[o] = bfbits(v - bf2f(h));
    }
}

// ---------------- fused poly combine + transposed split (+optional row split) ------
// v = ci*I + cx*X + cx2*X2 (+ Add); writes trsplit, optionally rowsplit.
__global__ void combine_split(const float* __restrict__ X, const float* __restrict__ X2,
                              const float* __restrict__ Add,
                              __nv_bfloat16* __restrict__ thi, __nv_bfloat16* __restrict__ tlo,
                              __nv_bfloat16* __restrict__ rhi, __nv_bfloat16* __restrict__ rlo,
                              float ci, float cx, float cx2) {
    __shared__ float tile[32][33];
    int x = blockIdx.x * 32 + threadIdx.x;
    int y = blockIdx.y * 32 + threadIdx.y;
#pragma unroll
    for (int i = 0; i < 32; i += 8) {
        size_t o = (size_t)(y + i) * N + x;
        float v = cx * X[o] + cx2 * X2[o];
        if (Add) v += Add[o];
        if (y + i == x) v += ci;
        if (rhi) {
            unsigned short h = bfbits(v);
            ((unsigned short*)rhi)[o] = h;
            ((unsigned short*)rlo)[o] = bfbits(v - bf2f(h));
        }
        tile[threadIdx.y + i][threadIdx.x] = v;
    }
    __syncthreads();
    x = blockIdx.y * 32 + threadIdx.x;
    y = blockIdx.x * 32 + threadIdx.y;
#pragma unroll
    for (int i = 0; i < 32; i += 8) {
        float v = tile[threadIdx.x][threadIdx.y + i];
        unsigned short h = bfbits(v);
        size_t o = (size_t)(y + i) * N + x;
        ((unsigned short*)thi)[o] = h;
        ((unsigned short*)tlo)[o] = bfbits(v - bf2f(h));
    }
}

// ---------------- plain transposed split ----------------
__global__ void split_tr(const float* __restrict__ in,
                         __nv_bfloat16* __restrict__ hi, __nv_bfloat16* __restrict__ lo) {
    __shared__ float tile[32][33];
    int x = blockIdx.x * 32 + threadIdx.x;
    int y = blockIdx.y * 32 + threadIdx.y;
#pragma unroll
    for (int i = 0; i < 32; i += 8)
        tile[threadIdx.y + i][threadIdx.x] = in[(size_t)(y + i) * N + x];
    __syncthreads();
    x = blockIdx.y * 32 + threadIdx.x;
    y = blockIdx.x * 32 + threadIdx.y;
#pragma unroll
    for (int i = 0; i < 32; i += 8) {
        float v = tile[threadIdx.x][threadIdx.y + i];
        unsigned short h = bfbits(v);
        size_t o = (size_t)(y + i) * N + x;
        ((unsigned short*)hi)[o] = h;
        ((unsigned short*)lo)[o] = bfbits(v - bf2f(h));
    }
}

// ================= mma.sync bf16x3 GEMM: C = A*B (fp32-equivalent) =================
// A' = [Ahi | Ahi | Alo] along K, B'^T = [Bhi | Blo | Bhi]  (B given as [N,K] row-major)
// 128x128 tile, 2 CTAs/SM. Optional fused row-split of C and smem-staged C^T store.
#define BM 128
#define BN 128
#define BK 64
#define STAGES 3
#define NCHUNK 192
#define ABYTES (BM * 128)
#define STAGE_BYTES (2 * BM * 128)            // 32768
#define GEMM_SMEM (STAGES * STAGE_BYTES)      // 98304

__device__ __forceinline__ void ldsm4(uint32_t& r0, uint32_t& r1, uint32_t& r2, uint32_t& r3,
                                      uint32_t addr) {
    asm volatile("ldmatrix.sync.aligned.m8n8.x4.shared.b16 {%0,%1,%2,%3}, [%4];"
                 : "=r"(r0), "=r"(r1), "=r"(r2), "=r"(r3) : "r"(addr));
}
__device__ __forceinline__ void mma16816(float* c, const uint32_t* a, uint32_t b0, uint32_t b1) {
    asm volatile("mma.sync.aligned.m16n8k16.row.col.f32.bf16.bf16.f32 "
                 "{%0,%1,%2,%3}, {%4,%5,%6,%7}, {%8,%9}, {%0,%1,%2,%3};"
                 : "+f"(c[0]), "+f"(c[1]), "+f"(c[2]), "+f"(c[3])
                 : "r"(a[0]), "r"(a[1]), "r"(a[2]), "r"(a[3]), "r"(b0), "r"(b1));
}

__global__ void __launch_bounds__(256, 2)
gemm_bf16x3(const __nv_bfloat16* __restrict__ Ahi, const __nv_bfloat16* __restrict__ Alo,
            const __nv_bfloat16* __restrict__ Bhi, const __nv_bfloat16* __restrict__ Blo,
            float* __restrict__ C,
            __nv_bfloat16* __restrict__ hiO, __nv_bfloat16* __restrict__ loO,
            float* __restrict__ trO) {
    extern __shared__ char smem[];
    const uint32_t sb = smem_u32(smem);
    const int tid = threadIdx.x;
    const int wid = tid >> 5, lane = tid & 31;
    const int wm = wid & 3, wn = wid >> 2;     // 4 warps M x 2 warps N, warp tile 32x64

    // L2-friendly tile swizzle: supertiles of 8 rows, column-major inside
    const int bid = blockIdx.x;
    const int grp = bid >> 8;                  // / (8*32)
    const int rem = bid & 255;
    const int m0 = (grp * 8 + (rem & 7)) * BM;
    const int n0 = (rem >> 3) * BN;

    // per-thread load offsets (A and B tiles have identical 128x128B shape)
    uint32_t goff[4], soff[4];
#pragma unroll
    for (int i = 0; i < 4; i++) {
        int q = tid + i * 256;
        int row = q >> 3, c16 = q & 7;
        goff[i] = (row << 12) + (c16 << 3);    // element offset within [128, 4096] slab
        soff[i] = SWZ(row * 128 + c16 * 16);
    }

    float acc[2][8][4];
#pragma unroll
    for (int i = 0; i < 2; i++)
#pragma unroll
        for (int j = 0; j < 8; j++)
#pragma unroll
            for (int k = 0; k < 4; k++) acc[i][j][k] = 0.f;

    auto load_chunk = [&](int c) {
        const int seg = c >> 6;
        const uint32_t k0 = (c & 63) << 6;
        const __nv_bfloat16* A = (seg == 2) ? Alo : Ahi;
        const __nv_bfloat16* B = (seg == 1) ? Blo : Bhi;
        const uint32_t st = sb + (c % STAGES) * STAGE_BYTES;
#pragma unroll
        for (int i = 0; i < 4; i++)
            cp16(st + soff[i], A + ((size_t)m0 << 12) + k0 + goff[i]);
#pragma unroll
        for (int i = 0; i < 4; i++)
            cp16(st + ABYTES + soff[i], B + ((size_t)n0 << 12) + k0 + goff[i]);
        asm volatile("cp.async.commit_group;" ::: "memory");
    };

    load_chunk(0);
    load_chunk(1);

    const int t = lane >> 3, r = lane & 7;
    const int arow0 = wm * 32 + (t & 1) * 8 + r;
    const int brow0 = wn * 64 + (t >> 1) * 8 + r;
    const uint32_t aoffk = (t >> 1) * 16;
    const uint32_t boffk = (t & 1) * 16;

    for (int c = 0; c < NCHUNK; c++) {
        asm volatile("cp.async.wait_group 1;" ::: "memory");
        __syncthreads();
        if (c + 2 < NCHUNK) load_chunk(c + 2);

        const uint32_t sA = sb + (c % STAGES) * STAGE_BYTES;
        const uint32_t sB = sA + ABYTES;

#pragma unroll
        for (int kk = 0; kk < 4; kk++) {
            uint32_t a[2][4], b[4][4];
#pragma unroll
            for (int mt = 0; mt < 2; mt++)
                ldsm4(a[mt][0], a[mt][1], a[mt][2], a[mt][3],
                      sA + SWZ((arow0 + mt * 16) * 128 + kk * 32 + aoffk));
#pragma unroll
            for (int j = 0; j < 4; j++)
                ldsm4(b[j][0], b[j][1], b[j][2], b[j][3],
                      sB + SWZ((brow0 + j * 16) * 128 + kk * 32 + boffk));
#pragma unroll
            for (int mt = 0; mt < 2; mt++)
#pragma unroll
                for (int nt = 0; nt < 8; nt++)
                    mma16816(acc[mt][nt], a[mt], b[nt >> 1][(nt & 1) * 2],
                             b[nt >> 1][(nt & 1) * 2 + 1]);
        }
        __syncthreads();
    }

    // ---- epilogue: C (+ optional fused row split) ----
    const int gp = lane >> 2, q = lane & 3;
#pragma unroll
    for (int mt = 0; mt < 2; mt++) {
        int mA = m0 + wm * 32 + mt * 16 + gp;
#pragma unroll
        for (int half = 0; half < 2; half++) {
            size_t rowo = (size_t)(mA + half * 8) * N;
#pragma unroll
            for (int nt = 0; nt < 8; nt++) {
                int n = n0 + wn * 64 + nt * 8 + q * 2;
                float c0 = acc[mt][nt][half * 2 + 0];
                float c1 = acc[mt][nt][half * 2 + 1];
                *(float2*)(C + rowo + n) = make_float2(c0, c1);
                if (hiO) {
                    *(uint32_t*)((unsigned short*)hiO + rowo + n) = packsplit_hi(c0, c1);
                    *(uint32_t*)((unsigned short*)loO + rowo + n) = packsplit_lo(c0, c1);
                }
            }
        }
    }

    // ---- optional transposed store via smem (128x129 fp32 = 66KB <= 96KB) ----
    if (trO) {
        __syncthreads();
        float* st = (float*)smem;
#pragma unroll
        for (int mt = 0; mt < 2; mt++) {
            int ml = wm * 32 + mt * 16 + gp;
#pragma unroll
            for (int half = 0; half < 2; half++)
#pragma unroll
                for (int nt = 0; nt < 8; nt++) {
                    int nl = wn * 64 + nt * 8 + q * 2;
                    st[(ml + half * 8) * 129 + nl + 0] = acc[mt][nt][half * 2 + 0];
                    st[(ml + half * 8) * 129 + nl + 1] = acc[mt][nt][half * 2 + 1];
                }
        }
        __syncthreads();
#pragma unroll
        for (int i = 0; i < 64; i++) {
            int idx = i * 256 + tid;
            int nn = idx >> 7, mm = idx & 127;
            trO[(size_t)(n0 + nn) * N + m0 + mm] = st[mm * 129 + nn];
        }
    }
}

// ---------------- per-row 16th-largest threshold (4-level byte histogram) ----------
__global__ __launch_bounds__(256) void topk_thresh(const float* __restrict__ H,
                                                   float* __restrict__ thr) {
    __shared__ unsigned sk[N];       // 16 KB
    __shared__ int hist[256];
    __shared__ int scan[256];
    __shared__ int sel_b, sel_above;
    const int row = blockIdx.x;
    const int tid = threadIdx.x;
    const int lane = tid & 31;
    const float* h = H + (size_t)row * N;

    for (int j = tid; j < N; j += 256) {
        unsigned u = __float_as_uint(h[j]);
        sk[j] = (u & 0x80000000u) ? ~u : (u | 0x80000000u);   // order-preserving
    }
    __syncthreads();

    unsigned prefix = 0;
    int k = 16;
#pragma unroll
    for (int lev = 0; lev < 4; lev++) {
        const int shift = 24 - lev * 8;
        const unsigned above_mask = (lev == 0) ? 0u : (0xFFFFFFFFu << (shift + 8));
        hist[tid] = 0;
        __syncthreads();
        for (int j = tid; j < N; j += 256) {
            unsigned key = sk[j];
            if ((key & above_mask) == prefix) {
                int bucket = (key >> shift) & 255;
                unsigned mm = __match_any_sync(__activemask(), bucket);
                int leader = __ffs(mm) - 1;
                if (lane == leader) atomicAdd(&hist[bucket], __popc(mm));
            }
        }
        __syncthreads();
        int s = hist[tid];
        scan[tid] = s;
        __syncthreads();
#pragma unroll
        for (int off = 1; off < 256; off <<= 1) {
            int v = (tid + off < 256) ? scan[tid + off] : 0;
            __syncthreads();
            scan[tid] += v;
            __syncthreads();
        }
        // scan[i] = #keys with bucket >= i (among candidates)
        int above = (tid == 255) ? 0 : scan[tid + 1];
        if (scan[tid] >= k && above < k) { sel_b = tid; sel_above = above; }
        __syncthreads();
        prefix |= ((unsigned)sel_b) << shift;
        k -= sel_above;
        __syncthreads();
    }
    if (tid == 0) {
        unsigned u = (prefix & 0x80000000u) ? (prefix & 0x7FFFFFFFu) : ~prefix;
        thr[row] = __uint_as_float(u);
    }
}

// ---------------- mask + symmetrize + I + row-normalize ----------------
__global__ __launch_bounds__(256) void finalize_kernel(const float* __restrict__ H,
                                                       const float* __restrict__ HT,
                                                       const float* __restrict__ thr,
                                                       float* __restrict__ out) {
    __shared__ float sthr[N];
    __shared__ float swarp[8];
    __shared__ float sinv;
    const int row = blockIdx.x;
    for (int j = threadIdx.x; j < N; j += 256) sthr[j] = thr[j];
    __syncthreads();

    const float ti = sthr[row];
    const float* h  = H  + (size_t)row * N;
    const float* ht = HT + (size_t)row * N;

    float s = 0.f;
    for (int j = threadIdx.x; j < N; j += 256) {
        float hij = h[j], hji = ht[j];
        if (hij >= ti || hji >= sthr[j]) s += 0.5f * (hij + hji);
    }
#pragma unroll
    for (int o = 16; o; o >>= 1) s += __shfl_down_sync(0xffffffffu, s, o);
    if ((threadIdx.x & 31) == 0) swarp[threadIdx.x >> 5] = s;
    __syncthreads();
    if (threadIdx.x == 0) {
        float tt = 0.f;
#pragma unroll
        for (int w = 0; w < 8; w++) tt += swarp[w];
        sinv = 1.0f / (tt + 1.0f);
    }
    __syncthreads();
    const float inv = sinv;

    for (int j = threadIdx.x; j < N; j += 256) {
        float hij = h[j], hji = ht[j];
        float v = (hij >= ti || hji >= sthr[j]) ? 0.5f * (hij + hji) : 0.f;
        if (j == row) v += 1.0f;
        out[(size_t)row * N + j] = v * inv;
    }
}

// ---------------- launch ----------------
extern "C" void kernel_launch(void* const* d_in, const int* in_sizes, int n_in,
                              void* d_out, int out_size) {
    const float* adj = (const float*)d_in[0];
    float* out = (float*)d_out;

    float *X, *X2, *T1, *H, *HT, *thr;
    __nv_bfloat16 *P1hi, *P1lo, *P2hi, *P2lo, *P3hi, *P3lo;
    cudaGetSymbolAddress((void**)&X,  g_X);
    cudaGetSymbolAddress((void**)&X2, g_X2);
    cudaGetSymbolAddress((void**)&T1, g_T1);
    cudaGetSymbolAddress((void**)&H,  g_H);
    cudaGetSymbolAddress((void**)&HT, g_HT);
    cudaGetSymbolAddress((void**)&thr, g_thr);
    cudaGetSymbolAddress((void**)&P1hi, g_P1hi);
    cudaGetSymbolAddress((void**)&P1lo, g_P1lo);
    cudaGetSymbolAddress((void**)&P2hi, g_P2hi);
    cudaGetSymbolAddress((void**)&P2lo, g_P2lo);
    cudaGetSymbolAddress((void**)&P3hi, g_P3hi);
    cudaGetSymbolAddress((void**)&P3lo, g_P3lo);

    cudaFuncSetAttribute(gemm_bf16x3, cudaFuncAttributeMaxDynamicSharedMemorySize, GEMM_SMEM);

    dim3 tgrid(N / 32, N / 32), tblk(32, 8);
    const int ggrid = (N / BM) * (N / BN);     // 1024

    // X = -1.25*adj ; P1 = rowsplit(X) ; P2 = trsplit(X)
    scale_split_both<<<tgrid, tblk>>>(adj, X, P1hi, P1lo, P2hi, P2lo, -1.25f);

    // X2 = X*X  (+ rowsplit -> P3)
    gemm_bf16x3<<<ggrid, 256, GEMM_SMEM>>>(P1hi, P1lo, P2hi, P2lo, X2, P3hi, P3lo, nullptr);
    // X3 = X2*X (+ rowsplit -> P1)
    gemm_bf16x3<<<ggrid, 256, GEMM_SMEM>>>(P3hi, P3lo, P2hi, P2lo, T1, P1hi, P1lo, nullptr);

    // A2 = I/720 + X/5040 + X2/40320  -> trsplit P2
    combine_split<<<tgrid, tblk>>>(X, X2, nullptr, P2hi, P2lo, nullptr, nullptr,
                                   1.0f / 720.0f, 1.0f / 5040.0f, 1.0f / 40320.0f);
    gemm_bf16x3<<<ggrid, 256, GEMM_SMEM>>>(P1hi, P1lo, P2hi, P2lo, T1, nullptr, nullptr, nullptr);

    // A1 + X3*A2 -> trsplit P2
    combine_split<<<tgrid, tblk>>>(X, X2, T1, P2hi, P2lo, nullptr, nullptr,
                                   1.0f / 6.0f, 1.0f / 24.0f, 1.0f / 120.0f);
    gemm_bf16x3<<<ggrid, 256, GEMM_SMEM>>>(P1hi, P1lo, P2hi, P2lo, T1, nullptr, nullptr, nullptr);

    // P = I + X + X2/2 + T1 -> rowsplit P1, trsplit P2
    combine_split<<<tgrid, tblk>>>(X, X2, T1, P2hi, P2lo, P1hi, P1lo, 1.0f, 1.0f, 0.5f);

    // P^2 (+ rowsplit -> P3)
    gemm_bf16x3<<<ggrid, 256, GEMM_SMEM>>>(P1hi, P1lo, P2hi, P2lo, T1, P3hi, P3lo, nullptr);
    split_tr<<<tgrid, tblk>>>(T1, P2hi, P2lo);
    // H = P^4, fused transposed store -> HT
    gemm_bf16x3<<<ggrid, 256, GEMM_SMEM>>>(P3hi, P3lo, P2hi, P2lo, H, nullptr, nullptr, HT);

    topk_thresh<<<N, 256>>>(H, thr);
    finalize_kernel<<<N, 256>>>(H, HT, thr, out);
}

// round 8
// speedup vs baseline: 3.8433x; 1.0157x over previous
#include <cuda_runtime.h>
#include <cuda_bf16.h>
#include <cstdint>
#include <cstddef>

#define N 4096
#define NNELEM ((size_t)N * (size_t)N)

// ---------------- static scratch (allocation-free rule) ----------------
__device__ float g_X [NNELEM];
__device__ float g_X2[NNELEM];
__device__ float g_T1[NNELEM];
__device__ float g_H [NNELEM];
__device__ float g_HT[NNELEM];
__device__ float g_thr[N];
__device__ __nv_bfloat16 g_P1hi[NNELEM];
__device__ __nv_bfloat16 g_P1lo[NNELEM];
__device__ __nv_bfloat16 g_P2hi[NNELEM];
__device__ __nv_bfloat16 g_P2lo[NNELEM];
__device__ __nv_bfloat16 g_P3hi[NNELEM];
__device__ __nv_bfloat16 g_P3lo[NNELEM];

// ---------------- helpers ----------------
__device__ __forceinline__ uint32_t smem_u32(const void* p) {
    return (uint32_t)__cvta_generic_to_shared(p);
}
__device__ __forceinline__ void cp16(uint32_t s, const void* g) {
    asm volatile("cp.async.cg.shared.global [%0], [%1], 16;" :: "r"(s), "l"(g));
}
#define SWZ(x) ((x) ^ (((x) >> 3) & 0x70))

__device__ __forceinline__ unsigned short bfbits(float f) {
    __nv_bfloat16 h = __float2bfloat16(f);
    return *reinterpret_cast<unsigned short*>(&h);
}
__device__ __forceinline__ float bf2f(unsigned short u) {
    __nv_bfloat16 h = *reinterpret_cast<__nv_bfloat16*>(&u);
    return __bfloat162float(h);
}
__device__ __forceinline__ uint32_t packsplit_hi(float a, float b) {
    return (uint32_t)bfbits(a) | ((uint32_t)bfbits(b) << 16);
}
__device__ __forceinline__ uint32_t packsplit_lo(float a, float b) {
    unsigned short ha = bfbits(a), hb = bfbits(b);
    return (uint32_t)bfbits(a - bf2f(ha)) | ((uint32_t)bfbits(b - bf2f(hb)) << 16);
}

// ---------------- fused scale + row split + transposed split ----------------
__global__ void scale_split_both(const float* __restrict__ in, float* __restrict__ X,
                                 __nv_bfloat16* __restrict__ rhi, __nv_bfloat16* __restrict__ rlo,
                                 __nv_bfloat16* __restrict__ thi, __nv_bfloat16* __restrict__ tlo,
                                 float a) {
    __shared__ float tile[32][33];
    int x = blockIdx.x * 32 + threadIdx.x;
    int y = blockIdx.y * 32 + threadIdx.y;
#pragma unroll
    for (int i = 0; i < 32; i += 8) {
        size_t o = (size_t)(y + i) * N + x;
        float v = in[o] * a;
        X[o] = v;
        unsigned short h = bfbits(v);
        ((unsigned short*)rhi)[o] = h;
        ((unsigned short*)rlo)[o] = bfbits(v - bf2f(h));
        tile[threadIdx.y + i][threadIdx.x] = v;
    }
    __syncthreads();
    x = blockIdx.y * 32 + threadIdx.x;
    y = blockIdx.x * 32 + threadIdx.y;
#pragma unroll
    for (int i = 0; i < 32; i += 8) {
        float v = tile[threadIdx.x][threadIdx.y + i];
        unsigned short h = bfbits(v);
        size_t o = (size_t)(y + i) * N + x;
        ((unsigned short*)thi)[o] = h;
        ((unsigned short*)tlo)[o] = bfbits(v - bf2f(h));
    }
}

// ---------------- fused poly combine + transposed split (+optional row split) ------
__global__ void combine_split(const float* __restrict__ X, const float* __restrict__ X2,
                              const float* __restrict__ Add,
                              __nv_bfloat16* __restrict__ thi, __nv_bfloat16* __restrict__ tlo,
                              __nv_bfloat16* __restrict__ rhi, __nv_bfloat16* __restrict__ rlo,
                              float ci, float cx, float cx2) {
    __shared__ float tile[32][33];
    int x = blockIdx.x * 32 + threadIdx.x;
    int y = blockIdx.y * 32 + threadIdx.y;
#pragma unroll
    for (int i = 0; i < 32; i += 8) {
        size_t o = (size_t)(y + i) * N + x;
        float v = cx * X[o] + cx2 * X2[o];
        if (Add) v += Add[o];
        if (y + i == x) v += ci;
        if (rhi) {
            unsigned short h = bfbits(v);
            ((unsigned short*)rhi)[o] = h;
            ((unsigned short*)rlo)[o] = bfbits(v - bf2f(h));
        }
        tile[threadIdx.y + i][threadIdx.x] = v;
    }
    __syncthreads();
    x = blockIdx.y * 32 + threadIdx.x;
    y = blockIdx.x * 32 + threadIdx.y;
#pragma unroll
    for (int i = 0; i < 32; i += 8) {
        float v = tile[threadIdx.x][threadIdx.y + i];
        unsigned short h = bfbits(v);
        size_t o = (size_t)(y + i) * N + x;
        ((unsigned short*)thi)[o] = h;
        ((unsigned short*)tlo)[o] = bfbits(v - bf2f(h));
    }
}

// ================= mma.sync bf16x3 GEMM: C = A*B (fp32-equivalent) =================
// A' = [Ahi | Ahi | Alo] along K, B'^T = [Bhi | Blo | Bhi]  (B given as [N,K] row-major)
// 128x128 tile, 2 CTAs/SM, single __syncthreads per chunk.
// Epilogue options: fp32 C, bf16 row-split, bf16 transposed split, fp32 transpose.
#define BM 128
#define BN 128
#define BK 64
#define STAGES 3
#define NCHUNK 192
#define ABYTES (BM * 128)
#define STAGE_BYTES (2 * BM * 128)            // 32768
#define GEMM_SMEM (STAGES * STAGE_BYTES)      // 98304

__device__ __forceinline__ void ldsm4(uint32_t& r0, uint32_t& r1, uint32_t& r2, uint32_t& r3,
                                      uint32_t addr) {
    asm volatile("ldmatrix.sync.aligned.m8n8.x4.shared.b16 {%0,%1,%2,%3}, [%4];"
                 : "=r"(r0), "=r"(r1), "=r"(r2), "=r"(r3) : "r"(addr));
}
__device__ __forceinline__ void mma16816(float* c, const uint32_t* a, uint32_t b0, uint32_t b1) {
    asm volatile("mma.sync.aligned.m16n8k16.row.col.f32.bf16.bf16.f32 "
                 "{%0,%1,%2,%3}, {%4,%5,%6,%7}, {%8,%9}, {%0,%1,%2,%3};"
                 : "+f"(c[0]), "+f"(c[1]), "+f"(c[2]), "+f"(c[3])
                 : "r"(a[0]), "r"(a[1]), "r"(a[2]), "r"(a[3]), "r"(b0), "r"(b1));
}

__global__ void __launch_bounds__(256, 2)
gemm_bf16x3(const __nv_bfloat16* __restrict__ Ahi, const __nv_bfloat16* __restrict__ Alo,
            const __nv_bfloat16* __restrict__ Bhi, const __nv_bfloat16* __restrict__ Blo,
            float* __restrict__ C,
            __nv_bfloat16* __restrict__ rhi, __nv_bfloat16* __restrict__ rlo,
            __nv_bfloat16* __restrict__ thiO, __nv_bfloat16* __restrict__ tloO,
            float* __restrict__ trF) {
    extern __shared__ char smem[];
    const uint32_t sb = smem_u32(smem);
    const int tid = threadIdx.x;
    const int wid = tid >> 5, lane = tid & 31;
    const int wm = wid & 3, wn = wid >> 2;     // warp tile 32x64

    // L2-friendly tile swizzle: supertiles of 16 m-tiles
    const int bid = blockIdx.x;
    const int grp = bid >> 9;
    const int rem = bid & 511;
    const int m0 = (grp * 16 + (rem & 15)) * BM;
    const int n0 = (rem >> 4) * BN;

    uint32_t goff[4], soff[4];
#pragma unroll
    for (int i = 0; i < 4; i++) {
        int q = tid + i * 256;
        int row = q >> 3, c16 = q & 7;
        goff[i] = (row << 12) + (c16 << 3);
        soff[i] = SWZ(row * 128 + c16 * 16);
    }

    float acc[2][8][4];
#pragma unroll
    for (int i = 0; i < 2; i++)
#pragma unroll
        for (int j = 0; j < 8; j++)
#pragma unroll
            for (int k = 0; k < 4; k++) acc[i][j][k] = 0.f;

    auto load_chunk = [&](int c) {
        const int seg = c >> 6;
        const uint32_t k0 = (c & 63) << 6;
        const __nv_bfloat16* A = (seg == 2) ? Alo : Ahi;
        const __nv_bfloat16* B = (seg == 1) ? Blo : Bhi;
        const uint32_t st = sb + (c % STAGES) * STAGE_BYTES;
#pragma unroll
        for (int i = 0; i < 4; i++)
            cp16(st + soff[i], A + ((size_t)m0 << 12) + k0 + goff[i]);
#pragma unroll
        for (int i = 0; i < 4; i++)
            cp16(st + ABYTES + soff[i], B + ((size_t)n0 << 12) + k0 + goff[i]);
        asm volatile("cp.async.commit_group;" ::: "memory");
    };

    load_chunk(0);
    load_chunk(1);

    const int t = lane >> 3, r = lane & 7;
    const int arow0 = wm * 32 + (t & 1) * 8 + r;
    const int brow0 = wn * 64 + (t >> 1) * 8 + r;
    const uint32_t aoffk = (t >> 1) * 16;
    const uint32_t boffk = (t & 1) * 16;

    for (int c = 0; c < NCHUNK; c++) {
        asm volatile("cp.async.wait_group 1;" ::: "memory");
        __syncthreads();          // single barrier: loads visible AND prior stage free
        if (c + 2 < NCHUNK) load_chunk(c + 2);
        else asm volatile("cp.async.commit_group;" ::: "memory");  // keep group accounting

        const uint32_t sA = sb + (c % STAGES) * STAGE_BYTES;
        const uint32_t sB = sA + ABYTES;

#pragma unroll
        for (int kk = 0; kk < 4; kk++) {
            uint32_t a[2][4], b[4][4];
#pragma unroll
            for (int mt = 0; mt < 2; mt++)
                ldsm4(a[mt][0], a[mt][1], a[mt][2], a[mt][3],
                      sA + SWZ((arow0 + mt * 16) * 128 + kk * 32 + aoffk));
#pragma unroll
            for (int j = 0; j < 4; j++)
                ldsm4(b[j][0], b[j][1], b[j][2], b[j][3],
                      sB + SWZ((brow0 + j * 16) * 128 + kk * 32 + boffk));
#pragma unroll
            for (int mt = 0; mt < 2; mt++)
#pragma unroll
                for (int nt = 0; nt < 8; nt++)
                    mma16816(acc[mt][nt], a[mt], b[nt >> 1][(nt & 1) * 2],
                             b[nt >> 1][(nt & 1) * 2 + 1]);
        }
    }

    // ---- epilogue: direct C / row split ----
    const int gp = lane >> 2, q = lane & 3;
    if (C || rhi) {
#pragma unroll
        for (int mt = 0; mt < 2; mt++) {
            int mA = m0 + wm * 32 + mt * 16 + gp;
#pragma unroll
            for (int half = 0; half < 2; half++) {
                size_t rowo = (size_t)(mA + half * 8) * N;
#pragma unroll
                for (int nt = 0; nt < 8; nt++) {
                    int n = n0 + wn * 64 + nt * 8 + q * 2;
                    float c0 = acc[mt][nt][half * 2 + 0];
                    float c1 = acc[mt][nt][half * 2 + 1];
                    if (C) *(float2*)(C + rowo + n) = make_float2(c0, c1);
                    if (rhi) {
                        *(uint32_t*)((unsigned short*)rhi + rowo + n) = packsplit_hi(c0, c1);
                        *(uint32_t*)((unsigned short*)rlo + rowo + n) = packsplit_lo(c0, c1);
                    }
                }
            }
        }
    }

    // ---- transposed outputs via smem staging (128x129 fp32 = 66KB) ----
    if (thiO || trF) {
        __syncthreads();
        float* st = (float*)smem;
#pragma unroll
        for (int mt = 0; mt < 2; mt++) {
            int ml = wm * 32 + mt * 16 + gp;
#pragma unroll
            for (int half = 0; half < 2; half++)
#pragma unroll
                for (int nt = 0; nt < 8; nt++) {
                    int nl = wn * 64 + nt * 8 + q * 2;
                    st[(ml + half * 8) * 129 + nl + 0] = acc[mt][nt][half * 2 + 0];
                    st[(ml + half * 8) * 129 + nl + 1] = acc[mt][nt][half * 2 + 1];
                }
        }
        __syncthreads();
#pragma unroll
        for (int i = 0; i < 64; i++) {
            int idx = i * 256 + tid;
            int nn = idx >> 7, mm = idx & 127;
            float v = st[mm * 129 + nn];
            size_t o = (size_t)(n0 + nn) * N + m0 + mm;
            if (trF) trF[o] = v;
            if (thiO) {
                unsigned short h = bfbits(v);
                ((unsigned short*)thiO)[o] = h;
                ((unsigned short*)tloO)[o] = bfbits(v - bf2f(h));
            }
        }
    }
}

// ---------------- per-row 16th-largest threshold (4-level byte histogram) ----------
__global__ __launch_bounds__(256) void topk_thresh(const float* __restrict__ H,
                                                   float* __restrict__ thr) {
    __shared__ unsigned sk[N];
    __shared__ int hist[256];
    __shared__ int scan[256];
    __shared__ int sel_b, sel_above;
    const int row = blockIdx.x;
    const int tid = threadIdx.x;
    const int lane = tid & 31;
    const float* h = H + (size_t)row * N;

    for (int j = tid; j < N; j += 256) {
        unsigned u = __float_as_uint(h[j]);
        sk[j] = (u & 0x80000000u) ? ~u : (u | 0x80000000u);
    }
    __syncthreads();

    unsigned prefix = 0;
    int k = 16;
#pragma unroll
    for (int lev = 0; lev < 4; lev++) {
        const int shift = 24 - lev * 8;
        const unsigned above_mask = (lev == 0) ? 0u : (0xFFFFFFFFu << (shift + 8));
        hist[tid] = 0;
        __syncthreads();
        for (int j = tid; j < N; j += 256) {
            unsigned key = sk[j];
            if ((key & above_mask) == prefix) {
                int bucket = (key >> shift) & 255;
                unsigned mm = __match_any_sync(__activemask(), bucket);
                int leader = __ffs(mm) - 1;
                if (lane == leader) atomicAdd(&hist[bucket], __popc(mm));
            }
        }
        __syncthreads();
        scan[tid] = hist[tid];
        __syncthreads();
#pragma unroll
        for (int off = 1; off < 256; off <<= 1) {
            int v = (tid + off < 256) ? scan[tid + off] : 0;
            __syncthreads();
            scan[tid] += v;
            __syncthreads();
        }
        int above = (tid == 255) ? 0 : scan[tid + 1];
        if (scan[tid] >= k && above < k) { sel_b = tid; sel_above = above; }
        __syncthreads();
        prefix |= ((unsigned)sel_b) << shift;
        k -= sel_above;
        __syncthreads();
    }
    if (tid == 0) {
        unsigned u = (prefix & 0x80000000u) ? (prefix & 0x7FFFFFFFu) : ~prefix;
        thr[row] = __uint_as_float(u);
    }
}

// ---------------- mask + symmetrize + I + row-normalize ----------------
__global__ __launch_bounds__(256) void finalize_kernel(const float* __restrict__ H,
                                                       const float* __restrict__ HT,
                                                       const float* __restrict__ thr,
                                                       float* __restrict__ out) {
    __shared__ float sthr[N];
    __shared__ float swarp[8];
    __shared__ float sinv;
    const int row = blockIdx.x;
    for (int j = threadIdx.x; j < N; j += 256) sthr[j] = thr[j];
    __syncthreads();

    const float ti = sthr[row];
    const float* h  = H  + (size_t)row * N;
    const float* ht = HT + (size_t)row * N;

    float s = 0.f;
    for (int j = threadIdx.x; j < N; j += 256) {
        float hij = h[j], hji = ht[j];
        if (hij >= ti || hji >= sthr[j]) s += 0.5f * (hij + hji);
    }
#pragma unroll
    for (int o = 16; o; o >>= 1) s += __shfl_down_sync(0xffffffffu, s, o);
    if ((threadIdx.x & 31) == 0) swarp[threadIdx.x >> 5] = s;
    __syncthreads();
    if (threadIdx.x == 0) {
        float tt = 0.f;
#pragma unroll
        for (int w = 0; w < 8; w++) tt += swarp[w];
        sinv = 1.0f / (tt + 1.0f);
    }
    __syncthreads();
    const float inv = sinv;

    for (int j = threadIdx.x; j < N; j += 256) {
        float hij = h[j], hji = ht[j];
        float v = (hij >= ti || hji >= sthr[j]) ? 0.5f * (hij + hji) : 0.f;
        if (j == row) v += 1.0f;
        out[(size_t)row * N + j] = v * inv;
    }
}

// ---------------- launch ----------------
extern "C" void kernel_launch(void* const* d_in, const int* in_sizes, int n_in,
                              void* d_out, int out_size) {
    const float* adj = (const float*)d_in[0];
    float* out = (float*)d_out;

    float *X, *X2, *T1, *H, *HT, *thr;
    __nv_bfloat16 *P1hi, *P1lo, *P2hi, *P2lo, *P3hi, *P3lo;
    cudaGetSymbolAddress((void**)&X,  g_X);
    cudaGetSymbolAddress((void**)&X2, g_X2);
    cudaGetSymbolAddress((void**)&T1, g_T1);
    cudaGetSymbolAddress((void**)&H,  g_H);
    cudaGetSymbolAddress((void**)&HT, g_HT);
    cudaGetSymbolAddress((void**)&thr, g_thr);
    cudaGetSymbolAddress((void**)&P1hi, g_P1hi);
    cudaGetSymbolAddress((void**)&P1lo, g_P1lo);
    cudaGetSymbolAddress((void**)&P2hi, g_P2hi);
    cudaGetSymbolAddress((void**)&P2lo, g_P2lo);
    cudaGetSymbolAddress((void**)&P3hi, g_P3hi);
    cudaGetSymbolAddress((void**)&P3lo, g_P3lo);

    cudaFuncSetAttribute(gemm_bf16x3, cudaFuncAttributeMaxDynamicSharedMemorySize, GEMM_SMEM);

    dim3 tgrid(N / 32, N / 32), tblk(32, 8);
    const int ggrid = (N / BM) * (N / BN);     // 1024

    // X = -1.25*adj ; P1 = rowsplit(X) ; P2 = trsplit(X)
    scale_split_both<<<tgrid, tblk>>>(adj, X, P1hi, P1lo, P2hi, P2lo, -1.25f);

    // X2 = X*X : C=X2 + rowsplit -> P3
    gemm_bf16x3<<<ggrid, 256, GEMM_SMEM>>>(P1hi, P1lo, P2hi, P2lo,
                                           X2, P3hi, P3lo, nullptr, nullptr, nullptr);
    // X3 = X2*X : rowsplit -> P1 only (fp32 never read)
    gemm_bf16x3<<<ggrid, 256, GEMM_SMEM>>>(P3hi, P3lo, P2hi, P2lo,
                                           nullptr, P1hi, P1lo, nullptr, nullptr, nullptr);

    // A2 = I/720 + X/5040 + X2/40320 -> trsplit P2
    combine_split<<<tgrid, tblk>>>(X, X2, nullptr, P2hi, P2lo, nullptr, nullptr,
                                   1.0f / 720.0f, 1.0f / 5040.0f, 1.0f / 40320.0f);
    gemm_bf16x3<<<ggrid, 256, GEMM_SMEM>>>(P1hi, P1lo, P2hi, P2lo,
                                           T1, nullptr, nullptr, nullptr, nullptr, nullptr);

    // A1 + X3*A2 -> trsplit P2
    combine_split<<<tgrid, tblk>>>(X, X2, T1, P2hi, P2lo, nullptr, nullptr,
                                   1.0f / 6.0f, 1.0f / 24.0f, 1.0f / 120.0f);
    gemm_bf16x3<<<ggrid, 256, GEMM_SMEM>>>(P1hi, P1lo, P2hi, P2lo,
                                           T1, nullptr, nullptr, nullptr, nullptr, nullptr);

    // P = I + X + X2/2 + T1 -> rowsplit P1 + trsplit P2
    combine_split<<<tgrid, tblk>>>(X, X2, T1, P2hi, P2lo, P1hi, P1lo, 1.0f, 1.0f, 0.5f);

    // P^2 : rowsplit -> P3, fused transposed split -> P2 (fp32 never read)
    gemm_bf16x3<<<ggrid, 256, GEMM_SMEM>>>(P1hi, P1lo, P2hi, P2lo,
                                           nullptr, P3hi, P3lo, P2hi, P2lo, nullptr);
    // H = P^4 : C=H + fused fp32 transpose -> HT
    gemm_bf16x3<<<ggrid, 256, GEMM_SMEM>>>(P3hi, P3lo, P2hi, P2lo,
                                           H, nullptr, nullptr, nullptr, nullptr, HT);

    topk_thresh<<<N, 256>>>(H, thr);
    finalize_kernel<<<N, 256>>>(H, HT, thr, out);
}

// round 9
// speedup vs baseline: 4.4881x; 1.1678x over previous
#include <cuda_runtime.h>
#include <cuda_bf16.h>
#include <cstdint>
#include <cstddef>
#include <cmath>

#define N 4096
#define NNELEM ((size_t)N * (size_t)N)

// ---------------- static scratch (allocation-free rule) ----------------
__device__ float g_X [NNELEM];
__device__ float g_X2[NNELEM];   // B1
__device__ float g_T1[NNELEM];   // B2
__device__ float g_H [NNELEM];
__device__ float g_HT[NNELEM];
__device__ float g_thr[N];
__device__ __nv_bfloat16 g_P1hi[NNELEM];
__device__ __nv_bfloat16 g_P1lo[NNELEM];
__device__ __nv_bfloat16 g_P2hi[NNELEM];
__device__ __nv_bfloat16 g_P2lo[NNELEM];
__device__ __nv_bfloat16 g_P3hi[NNELEM];
__device__ __nv_bfloat16 g_P3lo[NNELEM];
__device__ __nv_bfloat16 g_P4hi[NNELEM];
__device__ __nv_bfloat16 g_P4lo[NNELEM];

// ---------------- helpers ----------------
__device__ __forceinline__ uint32_t smem_u32(const void* p) {
    return (uint32_t)__cvta_generic_to_shared(p);
}
__device__ __forceinline__ void cp16(uint32_t s, const void* g) {
    asm volatile("cp.async.cg.shared.global [%0], [%1], 16;" :: "r"(s), "l"(g));
}
#define SWZ(x) ((x) ^ (((x) >> 3) & 0x70))

__device__ __forceinline__ unsigned short bfbits(float f) {
    __nv_bfloat16 h = __float2bfloat16(f);
    return *reinterpret_cast<unsigned short*>(&h);
}
__device__ __forceinline__ float bf2f(unsigned short u) {
    __nv_bfloat16 h = *reinterpret_cast<__nv_bfloat16*>(&u);
    return __bfloat162float(h);
}
__device__ __forceinline__ uint32_t packsplit_hi(float a, float b) {
    return (uint32_t)bfbits(a) | ((uint32_t)bfbits(b) << 16);
}
__device__ __forceinline__ uint32_t packsplit_lo(float a, float b) {
    unsigned short ha = bfbits(a), hb = bfbits(b);
    return (uint32_t)bfbits(a - bf2f(ha)) | ((uint32_t)bfbits(b - bf2f(hb)) << 16);
}

// ---------------- fused scale + row split + transposed split ----------------
__global__ void scale_split_both(const float* __restrict__ in, float* __restrict__ X,
                                 __nv_bfloat16* __restrict__ rhi, __nv_bfloat16* __restrict__ rlo,
                                 __nv_bfloat16* __restrict__ thi, __nv_bfloat16* __restrict__ tlo,
                                 float a) {
    __shared__ float tile[32][33];
    int x = blockIdx.x * 32 + threadIdx.x;
    int y = blockIdx.y * 32 + threadIdx.y;
#pragma unroll
    for (int i = 0; i < 32; i += 8) {
        size_t o = (size_t)(y + i) * N + x;
        float v = in[o] * a;
        X[o] = v;
        unsigned short h = bfbits(v);
        ((unsigned short*)rhi)[o] = h;
        ((unsigned short*)rlo)[o] = bfbits(v - bf2f(h));
        tile[threadIdx.y + i][threadIdx.x] = v;
    }
    __syncthreads();
    x = blockIdx.y * 32 + threadIdx.x;
    y = blockIdx.x * 32 + threadIdx.y;
#pragma unroll
    for (int i = 0; i < 32; i += 8) {
        float v = tile[threadIdx.x][threadIdx.y + i];
        unsigned short h = bfbits(v);
        size_t o = (size_t)(y + i) * N + x;
        ((unsigned short*)thi)[o] = h;
        ((unsigned short*)tlo)[o] = bfbits(v - bf2f(h));
    }
}

// ---------------- 3-input combine + transposed split ----------------
// v = ci*I + ca*A + cb*B + cc*C ; writes trsplit only
__global__ void combine3_ts(const float* __restrict__ A, const float* __restrict__ B,
                            const float* __restrict__ Cc,
                            __nv_bfloat16* __restrict__ thi, __nv_bfloat16* __restrict__ tlo,
                            float ci, float ca, float cb, float cc) {
    __shared__ float tile[32][33];
    int x = blockIdx.x * 32 + threadIdx.x;
    int y = blockIdx.y * 32 + threadIdx.y;
#pragma unroll
    for (int i = 0; i < 32; i += 8) {
        size_t o = (size_t)(y + i) * N + x;
        float v = ca * A[o] + cb * B[o];
        if (Cc) v += cc * Cc[o];
        if (y + i == x) v += ci;
        tile[threadIdx.y + i][threadIdx.x] = v;
    }
    __syncthreads();
    x = blockIdx.y * 32 + threadIdx.x;
    y = blockIdx.x * 32 + threadIdx.y;
#pragma unroll
    for (int i = 0; i < 32; i += 8) {
        float v = tile[threadIdx.x][threadIdx.y + i];
        unsigned short h = bfbits(v);
        size_t o = (size_t)(y + i) * N + x;
        ((unsigned short*)thi)[o] = h;
        ((unsigned short*)tlo)[o] = bfbits(v - bf2f(h));
    }
}

// ================= mma.sync bf16x3 GEMM: C = A*B (fp32-equivalent) =================
// A' = [Ahi | Ahi | Alo] along K, B'^T = [Bhi | Blo | Bhi]  (B given as [N,K] row-major)
// 128x128 tile, 2 CTAs/SM. Epilogue: raw fp32 C, plus affine transform
// w = cAcc*acc + cX*addX + cY*addY + ci*I applied to split outputs (rs opt-in via rsX).
#define BM 128
#define BN 128
#define BK 64
#define STAGES 3
#define NCHUNK 192
#define ABYTES (BM * 128)
#define STAGE_BYTES (2 * BM * 128)            // 32768
#define GEMM_SMEM (STAGES * STAGE_BYTES)      // 98304

__device__ __forceinline__ void ldsm4(uint32_t& r0, uint32_t& r1, uint32_t& r2, uint32_t& r3,
                                      uint32_t addr) {
    asm volatile("ldmatrix.sync.aligned.m8n8.x4.shared.b16 {%0,%1,%2,%3}, [%4];"
                 : "=r"(r0), "=r"(r1), "=r"(r2), "=r"(r3) : "r"(addr));
}
__device__ __forceinline__ void mma16816(float* c, const uint32_t* a, uint32_t b0, uint32_t b1) {
    asm volatile("mma.sync.aligned.m16n8k16.row.col.f32.bf16.bf16.f32 "
                 "{%0,%1,%2,%3}, {%4,%5,%6,%7}, {%8,%9}, {%0,%1,%2,%3};"
                 : "+f"(c[0]), "+f"(c[1]), "+f"(c[2]), "+f"(c[3])
                 : "r"(a[0]), "r"(a[1]), "r"(a[2]), "r"(a[3]), "r"(b0), "r"(b1));
}

__global__ void __launch_bounds__(256, 2)
gemm_bf16x3(const __nv_bfloat16* __restrict__ Ahi, const __nv_bfloat16* __restrict__ Alo,
            const __nv_bfloat16* __restrict__ Bhi, const __nv_bfloat16* __restrict__ Blo,
            float* __restrict__ C,
            const float* __restrict__ addX, const float* __restrict__ addY,
            float cAcc, float cX, float cY, float ci, int rsX,
            __nv_bfloat16* __restrict__ rhi, __nv_bfloat16* __restrict__ rlo,
            __nv_bfloat16* __restrict__ thi, __nv_bfloat16* __restrict__ tlo,
            float* __restrict__ trF) {
    extern __shared__ char smem[];
    const uint32_t sb = smem_u32(smem);
    const int tid = threadIdx.x;
    const int wid = tid >> 5, lane = tid & 31;
    const int wm = wid & 3, wn = wid >> 2;     // warp tile 32x64

    // L2-friendly tile swizzle: supertiles of 16 m-tiles
    const int bid = blockIdx.x;
    const int grp = bid >> 9;
    const int rem = bid & 511;
    const int m0 = (grp * 16 + (rem & 15)) * BM;
    const int n0 = (rem >> 4) * BN;

    uint32_t goff[4], soff[4];
#pragma unroll
    for (int i = 0; i < 4; i++) {
        int q = tid + i * 256;
        int row = q >> 3, c16 = q & 7;
        goff[i] = (row << 12) + (c16 << 3);
        soff[i] = SWZ(row * 128 + c16 * 16);
    }

    float acc[2][8][4];
#pragma unroll
    for (int i = 0; i < 2; i++)
#pragma unroll
        for (int j = 0; j < 8; j++)
#pragma unroll
            for (int k = 0; k < 4; k++) acc[i][j][k] = 0.f;

    auto load_chunk = [&](int c) {
        const int seg = c >> 6;
        const uint32_t k0 = (c & 63) << 6;
        const __nv_bfloat16* A = (seg == 2) ? Alo : Ahi;
        const __nv_bfloat16* B = (seg == 1) ? Blo : Bhi;
        const uint32_t st = sb + (c % STAGES) * STAGE_BYTES;
#pragma unroll
        for (int i = 0; i < 4; i++)
            cp16(st + soff[i], A + ((size_t)m0 << 12) + k0 + goff[i]);
#pragma unroll
        for (int i = 0; i < 4; i++)
            cp16(st + ABYTES + soff[i], B + ((size_t)n0 << 12) + k0 + goff[i]);
        asm volatile("cp.async.commit_group;" ::: "memory");
    };

    load_chunk(0);
    load_chunk(1);

    const int t = lane >> 3, r = lane & 7;
    const int arow0 = wm * 32 + (t & 1) * 8 + r;
    const int brow0 = wn * 64 + (t >> 1) * 8 + r;
    const uint32_t aoffk = (t >> 1) * 16;
    const uint32_t boffk = (t & 1) * 16;

    for (int c = 0; c < NCHUNK; c++) {
        asm volatile("cp.async.wait_group 1;" ::: "memory");
        __syncthreads();
        if (c + 2 < NCHUNK) load_chunk(c + 2);
        else asm volatile("cp.async.commit_group;" ::: "memory");

        const uint32_t sA = sb + (c % STAGES) * STAGE_BYTES;
        const uint32_t sB = sA + ABYTES;

#pragma unroll
        for (int kk = 0; kk < 4; kk++) {
            uint32_t a[2][4], b[4][4];
#pragma unroll
            for (int mt = 0; mt < 2; mt++)
                ldsm4(a[mt][0], a[mt][1], a[mt][2], a[mt][3],
                      sA + SWZ((arow0 + mt * 16) * 128 + kk * 32 + aoffk));
#pragma unroll
            for (int j = 0; j < 4; j++)
                ldsm4(b[j][0], b[j][1], b[j][2], b[j][3],
                      sB + SWZ((brow0 + j * 16) * 128 + kk * 32 + boffk));
#pragma unroll
            for (int mt = 0; mt < 2; mt++)
#pragma unroll
                for (int nt = 0; nt < 8; nt++)
                    mma16816(acc[mt][nt], a[mt], b[nt >> 1][(nt & 1) * 2],
                             b[nt >> 1][(nt & 1) * 2 + 1]);
        }
    }

    // ---- epilogue ----
    const int gp = lane >> 2, q = lane & 3;
    const bool doT = (thi != nullptr) || (trF != nullptr);
    float* st = (float*)smem;
    if (doT) __syncthreads();       // mainloop smem reads complete before st reuse

#pragma unroll
    for (int mt = 0; mt < 2; mt++)
#pragma unroll
        for (int half = 0; half < 2; half++) {
            int ml = wm * 32 + mt * 16 + half * 8 + gp;
            int mrow = m0 + ml;
            size_t rowo = (size_t)mrow * N;
#pragma unroll
            for (int nt = 0; nt < 8; nt++) {
                int nl = wn * 64 + nt * 8 + q * 2;
                int ncol = n0 + nl;
                size_t o = rowo + ncol;
                float c0 = acc[mt][nt][half * 2 + 0];
                float c1 = acc[mt][nt][half * 2 + 1];
                if (C) *(float2*)(C + o) = make_float2(c0, c1);
                float w0 = cAcc * c0, w1 = cAcc * c1;
                if (addX) { float2 ax = *(const float2*)(addX + o); w0 += cX * ax.x; w1 += cX * ax.y; }
                if (addY) { float2 ay = *(const float2*)(addY + o); w0 += cY * ay.x; w1 += cY * ay.y; }
                if (ci != 0.f) {
                    if (mrow == ncol)     w0 += ci;
                    if (mrow == ncol + 1) w1 += ci;
                }
                if (rhi) {
                    float r0 = rsX ? w0 : c0, r1 = rsX ? w1 : c1;
                    *(uint32_t*)((unsigned short*)rhi + o) = packsplit_hi(r0, r1);
                    *(uint32_t*)((unsigned short*)rlo + o) = packsplit_lo(r0, r1);
                }
                if (doT) { st[ml * 129 + nl] = w0; st[ml * 129 + nl + 1] = w1; }
            }
        }

    if (doT) {
        __syncthreads();
#pragma unroll
        for (int i = 0; i < 64; i++) {
            int idx = i * 256 + tid;
            int nn = idx >> 7, mm = idx & 127;
            float v = st[mm * 129 + nn];
            size_t o = (size_t)(n0 + nn) * N + m0 + mm;
            if (trF) trF[o] = v;
            if (thi) {
                unsigned short h = bfbits(v);
                ((unsigned short*)thi)[o] = h;
                ((unsigned short*)tlo)[o] = bfbits(v - bf2f(h));
            }
        }
    }
}

// ---------------- per-row 16th-largest threshold (4-level byte histogram) ----------
__global__ __launch_bounds__(256) void topk_thresh(const float* __restrict__ H,
                                                   float* __restrict__ thr) {
    __shared__ unsigned sk[N];
    __shared__ int hist[256];
    __shared__ int scan[256];
    __shared__ int sel_b, sel_above;
    const int row = blockIdx.x;
    const int tid = threadIdx.x;
    const int lane = tid & 31;
    const float* h = H + (size_t)row * N;

    for (int j = tid; j < N; j += 256) {
        unsigned u = __float_as_uint(h[j]);
        sk[j] = (u & 0x80000000u) ? ~u : (u | 0x80000000u);
    }
    __syncthreads();

    unsigned prefix = 0;
    int k = 16;
#pragma unroll
    for (int lev = 0; lev < 4; lev++) {
        const int shift = 24 - lev * 8;
        const unsigned above_mask = (lev == 0) ? 0u : (0xFFFFFFFFu << (shift + 8));
        hist[tid] = 0;
        __syncthreads();
        for (int j = tid; j < N; j += 256) {
            unsigned key = sk[j];
            if ((key & above_mask) == prefix) {
                int bucket = (key >> shift) & 255;
                unsigned mm = __match_any_sync(__activemask(), bucket);
                int leader = __ffs(mm) - 1;
                if (lane == leader) atomicAdd(&hist[bucket], __popc(mm));
            }
        }
        __syncthreads();
        scan[tid] = hist[tid];
        __syncthreads();
#pragma unroll
        for (int off = 1; off < 256; off <<= 1) {
            int v = (tid + off < 256) ? scan[tid + off] : 0;
            __syncthreads();
            scan[tid] += v;
            __syncthreads();
        }
        int above = (tid == 255) ? 0 : scan[tid + 1];
        if (scan[tid] >= k && above < k) { sel_b = tid; sel_above = above; }
        __syncthreads();
        prefix |= ((unsigned)sel_b) << shift;
        k -= sel_above;
        __syncthreads();
    }
    if (tid == 0) {
        unsigned u = (prefix & 0x80000000u) ? (prefix & 0x7FFFFFFFu) : ~prefix;
        thr[row] = __uint_as_float(u);
    }
}

// ---------------- mask + symmetrize + I + row-normalize ----------------
__global__ __launch_bounds__(256) void finalize_kernel(const float* __restrict__ H,
                                                       const float* __restrict__ HT,
                                                       const float* __restrict__ thr,
                                                       float* __restrict__ out) {
    __shared__ float sthr[N];
    __shared__ float swarp[8];
    __shared__ float sinv;
    const int row = blockIdx.x;
    for (int j = threadIdx.x; j < N; j += 256) sthr[j] = thr[j];
    __syncthreads();

    const float ti = sthr[row];
    const float* h  = H  + (size_t)row * N;
    const float* ht = HT + (size_t)row * N;

    float s = 0.f;
    for (int j = threadIdx.x; j < N; j += 256) {
        float hij = h[j], hji = ht[j];
        if (hij >= ti || hji >= sthr[j]) s += 0.5f * (hij + hji);
    }
#pragma unroll
    for (int o = 16; o; o >>= 1) s += __shfl_down_sync(0xffffffffu, s, o);
    if ((threadIdx.x & 31) == 0) swarp[threadIdx.x >> 5] = s;
    __syncthreads();
    if (threadIdx.x == 0) {
        float tt = 0.f;
#pragma unroll
        for (int w = 0; w < 8; w++) tt += swarp[w];
        sinv = 1.0f / (tt + 1.0f);
    }
    __syncthreads();
    const float inv = sinv;

    for (int j = threadIdx.x; j < N; j += 256) {
        float hij = h[j], hji = ht[j];
        float v = (hij >= ti || hji >= sthr[j]) ? 0.5f * (hij + hji) : 0.f;
        if (j == row) v += 1.0f;
        out[(size_t)row * N + j] = v * inv;
    }
}

// ---------------- launch ----------------
extern "C" void kernel_launch(void* const* d_in, const int* in_sizes, int n_in,
                              void* d_out, int out_size) {
    const float* adj = (const float*)d_in[0];
    float* out = (float*)d_out;

    float *X, *X2, *T1, *H, *HT, *thr;
    __nv_bfloat16 *P1hi, *P1lo, *P2hi, *P2lo, *P3hi, *P3lo, *P4hi, *P4lo;
    cudaGetSymbolAddress((void**)&X,  g_X);
    cudaGetSymbolAddress((void**)&X2, g_X2);
    cudaGetSymbolAddress((void**)&T1, g_T1);
    cudaGetSymbolAddress((void**)&H,  g_H);
    cudaGetSymbolAddress((void**)&HT, g_HT);
    cudaGetSymbolAddress((void**)&thr, g_thr);
    cudaGetSymbolAddress((void**)&P1hi, g_P1hi);
    cudaGetSymbolAddress((void**)&P1lo, g_P1lo);
    cudaGetSymbolAddress((void**)&P2hi, g_P2hi);
    cudaGetSymbolAddress((void**)&P2lo, g_P2lo);
    cudaGetSymbolAddress((void**)&P3hi, g_P3hi);
    cudaGetSymbolAddress((void**)&P3lo, g_P3lo);
    cudaGetSymbolAddress((void**)&P4hi, g_P4hi);
    cudaGetSymbolAddress((void**)&P4lo, g_P4lo);

    cudaFuncSetAttribute(gemm_bf16x3, cudaFuncAttributeMaxDynamicSharedMemorySize, GEMM_SMEM);

    // Bader-Blanes-Casas degree-8 Taylor coefficients (3 products).
    // Derived & verified against Taylor matching equations.
    const double s177 = sqrt(177.0);
    const double v2 = (1.0 + s177) / 528.0;                 // x2
    const double v1 = 4.0 * v2;                             // x1
    const double v7 = 1.0 / (40320.0 * v2 * v2);            // x7
    const double v5 = 11.0 / (2520.0 * v2);                 // x5
    const double v6 = 11.0 / (10080.0 * v2) - 11.0 / 420.0; // x6
    const double v4 = (61.0 / 2520.0 - (2.0 / 3.0) * v6) / v2;  // x4
    const double vy2 = 0.5 - (2.0 / 3.0) * v4;              // y2
    const float x1 = (float)v1, x2c = (float)v2, x3 = (float)(2.0 / 3.0);
    const float x4 = (float)v4, x5 = (float)v5, x6 = (float)v6, x7 = (float)v7;
    const float y2 = (float)vy2;

    dim3 tgrid(N / 32, N / 32), tblk(32, 8);
    const int ggrid = (N / BM) * (N / BN);     // 1024

    // X = -1.25*adj ; P1 = rs(X), P2 = ts(X)   (s=2 scaling, T=5)
    scale_split_both<<<tgrid, tblk>>>(adj, X, P1hi, P1lo, P2hi, P2lo, -1.25f);

    // G1: B1 = X*X. C=X2 raw, rs(raw)->P3 [A of G2], ts(x2*acc + x1*X)->P4 [B of G2]
    gemm_bf16x3<<<ggrid, 256, GEMM_SMEM>>>(P1hi, P1lo, P2hi, P2lo,
        X2, X, nullptr, x2c, x1, 0.f, 0.f, 0,
        P3hi, P3lo, P4hi, P4lo, nullptr);

    // G2: B2 = B1*(x1X + x2B1). C=T1 raw(B2), rs(acc + x3*B1)->P1 [A of G3]
    gemm_bf16x3<<<ggrid, 256, GEMM_SMEM>>>(P3hi, P3lo, P4hi, P4lo,
        T1, X2, nullptr, 1.f, x3, 0.f, 0.f, 1,
        P1hi, P1lo, nullptr, nullptr, nullptr);

    // M2 = x4*I + x5*X + x6*B1 + x7*B2 -> ts -> P2 [B of G3]
    combine3_ts<<<tgrid, tblk>>>(X, X2, T1, P2hi, P2lo, x4, x5, x6, x7);

    // G3: F = (x3B1+B2)*M2 + I + X + y2*B1. rs(F)->P3, ts(F)->P4
    gemm_bf16x3<<<ggrid, 256, GEMM_SMEM>>>(P1hi, P1lo, P2hi, P2lo,
        nullptr, X, X2, 1.f, 1.f, y2, 1.f, 1,
        P3hi, P3lo, P4hi, P4lo, nullptr);

    // G4: P = F^2. rs->P1, ts->P2
    gemm_bf16x3<<<ggrid, 256, GEMM_SMEM>>>(P3hi, P3lo, P4hi, P4lo,
        nullptr, nullptr, nullptr, 1.f, 0.f, 0.f, 0.f, 0,
        P1hi, P1lo, P2hi, P2lo, nullptr);

    // G5: H = P^2 = expm(-5*adj). C=H + fused fp32 transpose -> HT
    gemm_bf16x3<<<ggrid, 256, GEMM_SMEM>>>(P1hi, P1lo, P2hi, P2lo,
        H, nullptr, nullptr, 1.f, 0.f, 0.f, 0.f, 0,
        nullptr, nullptr, nullptr, nullptr, HT);

    topk_thresh<<<N, 256>>>(H, thr);
    finalize_kernel<<<N, 256>>>(H, HT, thr, out);
}

// round 10
// speedup vs baseline: 5.6000x; 1.2477x over previous
#include <cuda_runtime.h>
#include <cuda_bf16.h>
#include <cstdint>
#include <cstddef>
#include <cmath>

#define N 4096
#define NNELEM ((size_t)N * (size_t)N)

// ---------------- static scratch (allocation-free rule) ----------------
__device__ float g_X [NNELEM];
__device__ float g_X2[NNELEM];   // B1
__device__ float g_H [NNELEM];
__device__ float g_HT[NNELEM];
__device__ float g_thr[N];
__device__ __nv_bfloat16 g_P1hi[NNELEM];
__device__ __nv_bfloat16 g_P1lo[NNELEM];
__device__ __nv_bfloat16 g_P2hi[NNELEM];
__device__ __nv_bfloat16 g_P2lo[NNELEM];
__device__ __nv_bfloat16 g_P3hi[NNELEM];
__device__ __nv_bfloat16 g_P3lo[NNELEM];
__device__ __nv_bfloat16 g_P4hi[NNELEM];
__device__ __nv_bfloat16 g_P4lo[NNELEM];

// ---------------- helpers ----------------
__device__ __forceinline__ uint32_t smem_u32(const void* p) {
    return (uint32_t)__cvta_generic_to_shared(p);
}
__device__ __forceinline__ void cp16(uint32_t s, const void* g) {
    asm volatile("cp.async.cg.shared.global [%0], [%1], 16;" :: "r"(s), "l"(g));
}
#define SWZ(x) ((x) ^ (((x) >> 3) & 0x70))

__device__ __forceinline__ unsigned short bfbits(float f) {
    __nv_bfloat16 h = __float2bfloat16(f);
    return *reinterpret_cast<unsigned short*>(&h);
}
__device__ __forceinline__ float bf2f(unsigned short u) {
    __nv_bfloat16 h = *reinterpret_cast<__nv_bfloat16*>(&u);
    return __bfloat162float(h);
}
__device__ __forceinline__ uint32_t packsplit_hi(float a, float b) {
    return (uint32_t)bfbits(a) | ((uint32_t)bfbits(b) << 16);
}
__device__ __forceinline__ uint32_t packsplit_lo(float a, float b) {
    unsigned short ha = bfbits(a), hb = bfbits(b);
    return (uint32_t)bfbits(a - bf2f(ha)) | ((uint32_t)bfbits(b - bf2f(hb)) << 16);
}

// ---------------- fused scale + row split + transposed split ----------------
__global__ void scale_split_both(const float* __restrict__ in, float* __restrict__ X,
                                 __nv_bfloat16* __restrict__ rhi, __nv_bfloat16* __restrict__ rlo,
                                 __nv_bfloat16* __restrict__ thi, __nv_bfloat16* __restrict__ tlo,
                                 float a) {
    __shared__ float tile[32][33];
    int x = blockIdx.x * 32 + threadIdx.x;
    int y = blockIdx.y * 32 + threadIdx.y;
#pragma unroll
    for (int i = 0; i < 32; i += 8) {
        size_t o = (size_t)(y + i) * N + x;
        float v = in[o] * a;
        X[o] = v;
        unsigned short h = bfbits(v);
        ((unsigned short*)rhi)[o] = h;
        ((unsigned short*)rlo)[o] = bfbits(v - bf2f(h));
        tile[threadIdx.y + i][threadIdx.x] = v;
    }
    __syncthreads();
    x = blockIdx.y * 32 + threadIdx.x;
    y = blockIdx.x * 32 + threadIdx.y;
#pragma unroll
    for (int i = 0; i < 32; i += 8) {
        float v = tile[threadIdx.x][threadIdx.y + i];
        unsigned short h = bfbits(v);
        size_t o = (size_t)(y + i) * N + x;
        ((unsigned short*)thi)[o] = h;
        ((unsigned short*)tlo)[o] = bfbits(v - bf2f(h));
    }
}

// ================= mma.sync bf16x3 GEMM: C = A*B (fp32-equivalent) =================
// A' = [Ahi | Ahi | Alo] along K, B'^T = [Bhi | Blo | Bhi]  (B given as [N,K] row-major)
// 128x128 tile, 2 CTAs/SM. Dual-combo epilogue:
//   wR = cR0*acc + cR1*addX + cR2*addY + cRi*I   -> row-split (rhi/rlo)
//   wT = cT0*acc + cT1*addX + cT2*addY + cTi*I   -> transposed split (thi/tlo) / fp32 trF
// Raw fp32 acc optionally stored to C.
#define BM 128
#define BN 128
#define BK 64
#define STAGES 3
#define NCHUNK 192
#define ABYTES (BM * 128)
#define STAGE_BYTES (2 * BM * 128)            // 32768
#define GEMM_SMEM (STAGES * STAGE_BYTES)      // 98304

__device__ __forceinline__ void ldsm4(uint32_t& r0, uint32_t& r1, uint32_t& r2, uint32_t& r3,
                                      uint32_t addr) {
    asm volatile("ldmatrix.sync.aligned.m8n8.x4.shared.b16 {%0,%1,%2,%3}, [%4];"
                 : "=r"(r0), "=r"(r1), "=r"(r2), "=r"(r3) : "r"(addr));
}
__device__ __forceinline__ void mma16816(float* c, const uint32_t* a, uint32_t b0, uint32_t b1) {
    asm volatile("mma.sync.aligned.m16n8k16.row.col.f32.bf16.bf16.f32 "
                 "{%0,%1,%2,%3}, {%4,%5,%6,%7}, {%8,%9}, {%0,%1,%2,%3};"
                 : "+f"(c[0]), "+f"(c[1]), "+f"(c[2]), "+f"(c[3])
                 : "r"(a[0]), "r"(a[1]), "r"(a[2]), "r"(a[3]), "r"(b0), "r"(b1));
}

__global__ void __launch_bounds__(256, 2)
gemm_bf16x3(const __nv_bfloat16* __restrict__ Ahi, const __nv_bfloat16* __restrict__ Alo,
            const __nv_bfloat16* __restrict__ Bhi, const __nv_bfloat16* __restrict__ Blo,
            float* __restrict__ C,
            const float* __restrict__ addX, const float* __restrict__ addY,
            float cR0, float cR1, float cR2, float cRi,
            float cT0, float cT1, float cT2, float cTi,
            __nv_bfloat16* __restrict__ rhi, __nv_bfloat16* __restrict__ rlo,
            __nv_bfloat16* __restrict__ thi, __nv_bfloat16* __restrict__ tlo,
            float* __restrict__ trF) {
    extern __shared__ char smem[];
    const uint32_t sb = smem_u32(smem);
    const int tid = threadIdx.x;
    const int wid = tid >> 5, lane = tid & 31;
    const int wm = wid & 3, wn = wid >> 2;     // warp tile 32x64

    // L2-friendly tile swizzle: supertiles of 16 m-tiles
    const int bid = blockIdx.x;
    const int grp = bid >> 9;
    const int rem = bid & 511;
    const int m0 = (grp * 16 + (rem & 15)) * BM;
    const int n0 = (rem >> 4) * BN;

    uint32_t goff[4], soff[4];
#pragma unroll
    for (int i = 0; i < 4; i++) {
        int q = tid + i * 256;
        int row = q >> 3, c16 = q & 7;
        goff[i] = (row << 12) + (c16 << 3);
        soff[i] = SWZ(row * 128 + c16 * 16);
    }

    float acc[2][8][4];
#pragma unroll
    for (int i = 0; i < 2; i++)
#pragma unroll
        for (int j = 0; j < 8; j++)
#pragma unroll
            for (int k = 0; k < 4; k++) acc[i][j][k] = 0.f;

    auto load_chunk = [&](int c) {
        const int seg = c >> 6;
        const uint32_t k0 = (c & 63) << 6;
        const __nv_bfloat16* A = (seg == 2) ? Alo : Ahi;
        const __nv_bfloat16* B = (seg == 1) ? Blo : Bhi;
        const uint32_t st = sb + (c % STAGES) * STAGE_BYTES;
#pragma unroll
        for (int i = 0; i < 4; i++)
            cp16(st + soff[i], A + ((size_t)m0 << 12) + k0 + goff[i]);
#pragma unroll
        for (int i = 0; i < 4; i++)
            cp16(st + ABYTES + soff[i], B + ((size_t)n0 << 12) + k0 + goff[i]);
        asm volatile("cp.async.commit_group;" ::: "memory");
    };

    load_chunk(0);
    load_chunk(1);

    const int t = lane >> 3, r = lane & 7;
    const int arow0 = wm * 32 + (t & 1) * 8 + r;
    const int brow0 = wn * 64 + (t >> 1) * 8 + r;
    const uint32_t aoffk = (t >> 1) * 16;
    const uint32_t boffk = (t & 1) * 16;

    for (int c = 0; c < NCHUNK; c++) {
        asm volatile("cp.async.wait_group 1;" ::: "memory");
        __syncthreads();
        if (c + 2 < NCHUNK) load_chunk(c + 2);
        else asm volatile("cp.async.commit_group;" ::: "memory");

        const uint32_t sA = sb + (c % STAGES) * STAGE_BYTES;
        const uint32_t sB = sA + ABYTES;

#pragma unroll
        for (int kk = 0; kk < 4; kk++) {
            uint32_t a[2][4], b[4][4];
#pragma unroll
            for (int mt = 0; mt < 2; mt++)
                ldsm4(a[mt][0], a[mt][1], a[mt][2], a[mt][3],
                      sA + SWZ((arow0 + mt * 16) * 128 + kk * 32 + aoffk));
#pragma unroll
            for (int j = 0; j < 4; j++)
                ldsm4(b[j][0], b[j][1], b[j][2], b[j][3],
                      sB + SWZ((brow0 + j * 16) * 128 + kk * 32 + boffk));
#pragma unroll
            for (int mt = 0; mt < 2; mt++)
#pragma unroll
                for (int nt = 0; nt < 8; nt++)
                    mma16816(acc[mt][nt], a[mt], b[nt >> 1][(nt & 1) * 2],
                             b[nt >> 1][(nt & 1) * 2 + 1]);
        }
    }

    // ---- epilogue ----
    const int gp = lane >> 2, q = lane & 3;
    const bool doT = (thi != nullptr) || (trF != nullptr);
    float* st = (float*)smem;
    if (doT) __syncthreads();       // mainloop smem reads complete before st reuse

#pragma unroll
    for (int mt = 0; mt < 2; mt++)
#pragma unroll
        for (int half = 0; half < 2; half++) {
            int ml = wm * 32 + mt * 16 + half * 8 + gp;
            int mrow = m0 + ml;
            size_t rowo = (size_t)mrow * N;
#pragma unroll
            for (int nt = 0; nt < 8; nt++) {
                int nl = wn * 64 + nt * 8 + q * 2;
                int ncol = n0 + nl;
                size_t o = rowo + ncol;
                float c0 = acc[mt][nt][half * 2 + 0];
                float c1 = acc[mt][nt][half * 2 + 1];
                if (C) *(float2*)(C + o) = make_float2(c0, c1);
                float ax0 = 0.f, ax1 = 0.f, ay0 = 0.f, ay1 = 0.f;
                if (addX) { float2 v = *(const float2*)(addX + o); ax0 = v.x; ax1 = v.y; }
                if (addY) { float2 v = *(const float2*)(addY + o); ay0 = v.x; ay1 = v.y; }
                float d0 = (mrow == ncol) ? 1.f : 0.f;
                float d1 = (mrow == ncol + 1) ? 1.f : 0.f;
                if (rhi) {
                    float w0 = cR0 * c0 + cR1 * ax0 + cR2 * ay0 + cRi * d0;
                    float w1 = cR0 * c1 + cR1 * ax1 + cR2 * ay1 + cRi * d1;
                    *(uint32_t*)((unsigned short*)rhi + o) = packsplit_hi(w0, w1);
                    *(uint32_t*)((unsigned short*)rlo + o) = packsplit_lo(w0, w1);
                }
                if (doT) {
                    float w0 = cT0 * c0 + cT1 * ax0 + cT2 * ay0 + cTi * d0;
                    float w1 = cT0 * c1 + cT1 * ax1 + cT2 * ay1 + cTi * d1;
                    st[ml * 129 + nl] = w0;
                    st[ml * 129 + nl + 1] = w1;
                }
            }
        }

    if (doT) {
        __syncthreads();
#pragma unroll
        for (int i = 0; i < 64; i++) {
            int idx = i * 256 + tid;
            int nn = idx >> 7, mm = idx & 127;
            float v = st[mm * 129 + nn];
            size_t o = (size_t)(n0 + nn) * N + m0 + mm;
            if (trF) trF[o] = v;
            if (thi) {
                unsigned short h = bfbits(v);
                ((unsigned short*)thi)[o] = h;
                ((unsigned short*)tlo)[o] = bfbits(v - bf2f(h));
            }
        }
    }
}

// ---------------- per-row 16th-largest threshold (4-level byte histogram) ----------
__global__ __launch_bounds__(256) void topk_thresh(const float* __restrict__ H,
                                                   float* __restrict__ thr) {
    __shared__ unsigned sk[N];
    __shared__ int hist[256];
    __shared__ int scan[256];
    __shared__ int sel_b, sel_above;
    const int row = blockIdx.x;
    const int tid = threadIdx.x;
    const int lane = tid & 31;
    const float* h = H + (size_t)row * N;

    for (int j = tid; j < N; j += 256) {
        unsigned u = __float_as_uint(h[j]);
        sk[j] = (u & 0x80000000u) ? ~u : (u | 0x80000000u);
    }
    __syncthreads();

    unsigned prefix = 0;
    int k = 16;
#pragma unroll
    for (int lev = 0; lev < 4; lev++) {
        const int shift = 24 - lev * 8;
        const unsigned above_mask = (lev == 0) ? 0u : (0xFFFFFFFFu << (shift + 8));
        hist[tid] = 0;
        __syncthreads();
        for (int j = tid; j < N; j += 256) {
            unsigned key = sk[j];
            if ((key & above_mask) == prefix) {
                int bucket = (key >> shift) & 255;
                unsigned mm = __match_any_sync(__activemask(), bucket);
                int leader = __ffs(mm) - 1;
                if (lane == leader) atomicAdd(&hist[bucket], __popc(mm));
            }
        }
        __syncthreads();
        scan[tid] = hist[tid];
        __syncthreads();
#pragma unroll
        for (int off = 1; off < 256; off <<= 1) {
            int v = (tid + off < 256) ? scan[tid + off] : 0;
            __syncthreads();
            scan[tid] += v;
            __syncthreads();
        }
        int above = (tid == 255) ? 0 : scan[tid + 1];
        if (scan[tid] >= k && above < k) { sel_b = tid; sel_above = above; }
        __syncthreads();
        prefix |= ((unsigned)sel_b) << shift;
        k -= sel_above;
        __syncthreads();
    }
    if (tid == 0) {
        unsigned u = (prefix & 0x80000000u) ? (prefix & 0x7FFFFFFFu) : ~prefix;
        thr[row] = __uint_as_float(u);
    }
}

// ---------------- mask + symmetrize + I + row-normalize ----------------
__global__ __launch_bounds__(256) void finalize_kernel(const float* __restrict__ H,
                                                       const float* __restrict__ HT,
                                                       const float* __restrict__ thr,
                                                       float* __restrict__ out) {
    __shared__ float sthr[N];
    __shared__ float swarp[8];
    __shared__ float sinv;
    const int row = blockIdx.x;
    for (int j = threadIdx.x; j < N; j += 256) sthr[j] = thr[j];
    __syncthreads();

    const float ti = sthr[row];
    const float* h  = H  + (size_t)row * N;
    const float* ht = HT + (size_t)row * N;

    float s = 0.f;
    for (int j = threadIdx.x; j < N; j += 256) {
        float hij = h[j], hji = ht[j];
        if (hij >= ti || hji >= sthr[j]) s += 0.5f * (hij + hji);
    }
#pragma unroll
    for (int o = 16; o; o >>= 1) s += __shfl_down_sync(0xffffffffu, s, o);
    if ((threadIdx.x & 31) == 0) swarp[threadIdx.x >> 5] = s;
    __syncthreads();
    if (threadIdx.x == 0) {
        float tt = 0.f;
#pragma unroll
        for (int w = 0; w < 8; w++) tt += swarp[w];
        sinv = 1.0f / (tt + 1.0f);
    }
    __syncthreads();
    const float inv = sinv;

    for (int j = threadIdx.x; j < N; j += 256) {
        float hij = h[j], hji = ht[j];
        float v = (hij >= ti || hji >= sthr[j]) ? 0.5f * (hij + hji) : 0.f;
        if (j == row) v += 1.0f;
        out[(size_t)row * N + j] = v * inv;
    }
}

// ---------------- launch ----------------
extern "C" void kernel_launch(void* const* d_in, const int* in_sizes, int n_in,
                              void* d_out, int out_size) {
    const float* adj = (const float*)d_in[0];
    float* out = (float*)d_out;

    float *X, *X2, *H, *HT, *thr;
    __nv_bfloat16 *P1hi, *P1lo, *P2hi, *P2lo, *P3hi, *P3lo, *P4hi, *P4lo;
    cudaGetSymbolAddress((void**)&X,  g_X);
    cudaGetSymbolAddress((void**)&X2, g_X2);
    cudaGetSymbolAddress((void**)&H,  g_H);
    cudaGetSymbolAddress((void**)&HT, g_HT);
    cudaGetSymbolAddress((void**)&thr, g_thr);
    cudaGetSymbolAddress((void**)&P1hi, g_P1hi);
    cudaGetSymbolAddress((void**)&P1lo, g_P1lo);
    cudaGetSymbolAddress((void**)&P2hi, g_P2hi);
    cudaGetSymbolAddress((void**)&P2lo, g_P2lo);
    cudaGetSymbolAddress((void**)&P3hi, g_P3hi);
    cudaGetSymbolAddress((void**)&P3lo, g_P3lo);
    cudaGetSymbolAddress((void**)&P4hi, g_P4hi);
    cudaGetSymbolAddress((void**)&P4lo, g_P4lo);

    cudaFuncSetAttribute(gemm_bf16x3, cudaFuncAttributeMaxDynamicSharedMemorySize, GEMM_SMEM);

    // Bader-Blanes-Casas degree-8 Taylor coefficients (3 products).
    const double s177 = sqrt(177.0);
    const double v2 = (1.0 + s177) / 528.0;                 // x2
    const double v1 = 4.0 * v2;                             // x1
    const double v7 = 1.0 / (40320.0 * v2 * v2);            // x7
    const double v5 = 11.0 / (2520.0 * v2);                 // x5
    const double v6 = 11.0 / (10080.0 * v2) - 11.0 / 420.0; // x6
    const double v4 = (61.0 / 2520.0 - (2.0 / 3.0) * v6) / v2;  // x4
    const double vy2 = 0.5 - (2.0 / 3.0) * v4;              // y2
    const float x1 = (float)v1, x2c = (float)v2, x3 = (float)(2.0 / 3.0);
    const float x4 = (float)v4, x5 = (float)v5, x6 = (float)v6, x7 = (float)v7;
    const float y2 = (float)vy2;

    dim3 tgrid(N / 32, N / 32), tblk(32, 8);
    const int ggrid = (N / BM) * (N / BN);     // 1024

    // s = 1 scaling: X = -2.5*adj ; P1 = rs(X), P2 = ts(X)
    scale_split_both<<<tgrid, tblk>>>(adj, X, P1hi, P1lo, P2hi, P2lo, -2.5f);

    // G1: B1 = X*X. C=X2 raw; rs(raw)->P3 [A of G2]; ts(x2*acc + x1*X)->P4 [B of G2]
    gemm_bf16x3<<<ggrid, 256, GEMM_SMEM>>>(P1hi, P1lo, P2hi, P2lo,
        X2, X, nullptr,
        1.f, 0.f, 0.f, 0.f,          // wR = raw B1
        x2c, x1, 0.f, 0.f,           // wT = x2*B1 + x1*X
        P3hi, P3lo, P4hi, P4lo, nullptr);

    // G2: B2 = B1*(x1X + x2B1). rs(acc + x3*B1)->P1 [A of G3];
    //     ts(x7*acc + x6*B1 + x5*X + x4*I)->P2 [B of G3 = M2]. No fp32 C.
    gemm_bf16x3<<<ggrid, 256, GEMM_SMEM>>>(P3hi, P3lo, P4hi, P4lo,
        nullptr, X2, X,
        1.f, x3, 0.f, 0.f,           // wR = B2 + x3*B1
        x7, x6, x5, x4,              // wT = x7*B2 + x6*B1 + x5*X + x4*I
        P1hi, P1lo, P2hi, P2lo, nullptr);

    // G3: F = (x3B1+B2)*M2 + I + X + y2*B1. rs(w)->P3, ts(w)->P4; w = acc + X + y2*B1 + I
    gemm_bf16x3<<<ggrid, 256, GEMM_SMEM>>>(P1hi, P1lo, P2hi, P2lo,
        nullptr, X, X2,
        1.f, 1.f, y2, 1.f,
        1.f, 1.f, y2, 1.f,
        P3hi, P3lo, P4hi, P4lo, nullptr);

    // G4: H = F^2 = expm(-5*adj). C=H + fused fp32 transpose -> HT
    gemm_bf16x3<<<ggrid, 256, GEMM_SMEM>>>(P3hi, P3lo, P4hi, P4lo,
        H, nullptr, nullptr,
        0.f, 0.f, 0.f, 0.f,
        1.f, 0.f, 0.f, 0.f,
        nullptr, nullptr, nullptr, nullptr, HT);

    topk_thresh<<<N, 256>>>(H, thr);
    finalize_kernel<<<N, 256>>>(H, HT, thr, out);
}